// round 2
// baseline (speedup 1.0000x reference)
#include <cuda_runtime.h>
#include <math.h>

// Problem constants
#define HD 256          // hidden dim
#define GG 768          // 3*H gates
#define NSENT 2048      // R*S sentences
#define NWORD 64        // words per sentence
#define NREV 64         // reviews
#define SPR 32          // sentences per review
#define DREV 276        // H + UF
#define UF 20

// ---------------- scratch (static device arrays; no allocation allowed) ----------------
__device__ float g_wgT_ih[2 * 256 * GG];
__device__ float g_wgT_hh[2 * 256 * GG];
__device__ float g_sgT_ih[2 * 256 * GG];
__device__ float g_sgT_hh[2 * 256 * GG];
__device__ float g_rgT_ih[2 * DREV * GG];
__device__ float g_rgT_hh[2 * 256 * GG];
__device__ float g_sent[2 * NSENT * HD];   // word-GRU final states per dir
__device__ float g_rev[2 * NREV * HD];     // sentence-GRU final states per dir
__device__ float g_pbatch[NREV * DREV];    // [64][276]
__device__ float g_doc[2 * HD];            // review-GRU final states per dir

__device__ __forceinline__ float sigf(float x) { return 1.0f / (1.0f + __expf(-x)); }

__device__ __forceinline__ float seluf(float x) {
    const float alpha = 1.6732632423543772f;
    const float scale = 1.0507009873554805f;
    return x > 0.0f ? scale * x : scale * alpha * (expf(x) - 1.0f);
}

// ---------------- weight transpose: src [2][768][Din] -> dst [2][Din][768] ----------------
__global__ void transpose_kernel(const float* __restrict__ src, float* __restrict__ dst, int Din) {
    int idx = blockIdx.x * blockDim.x + threadIdx.x;
    int total = 2 * GG * Din;
    if (idx >= total) return;
    int g = idx % GG;
    int rem = idx / GG;
    int k = rem % Din;
    int d = rem / Din;
    dst[idx] = src[(d * GG + g) * Din + k];
}

// ---------------- generic bi-GRU block kernel ----------------
// MODE 0: word level  — x gathered from embedding via word indices
// MODE 1: sent level  — x = sent_fwd + sent_bwd
// MODE 2: review level— x = p_batch row (batch 1)
// Thread t owns gate dims {t, t+256, t+512} and hidden dim t.
template <int MODE, int ROWS, int T, int D>
__global__ void gru_kernel(const int* __restrict__ widx,
                           const float* __restrict__ embed,
                           const float* __restrict__ xin0,
                           const float* __restrict__ xin1,
                           const float* __restrict__ wT_ih,
                           const float* __restrict__ wT_hh,
                           const float* __restrict__ bih,
                           const float* __restrict__ bhh,
                           float* __restrict__ out, int nbatch) {
    const int dir  = blockIdx.y;
    const int row0 = blockIdx.x * ROWS;
    const int t0   = threadIdx.x;  // 0..255

    __shared__ float sx[ROWS][D];
    __shared__ float sh[ROWS][HD];

#pragma unroll
    for (int r = 0; r < ROWS; r++) sh[r][t0] = 0.0f;

    const float* wih = wT_ih + dir * D * GG;
    const float* whh = wT_hh + dir * HD * GG;
    const float bi0 = bih[dir * GG + t0];
    const float bi1 = bih[dir * GG + 256 + t0];
    const float bi2 = bih[dir * GG + 512 + t0];
    const float bh0 = bhh[dir * GG + t0];
    const float bh1 = bhh[dir * GG + 256 + t0];
    const float bh2 = bhh[dir * GG + 512 + t0];

    for (int t = 0; t < T; t++) {
        const int te = dir ? (T - 1 - t) : t;

        // ---- load x tile ----
        if (MODE == 0) {
#pragma unroll
            for (int r = 0; r < ROWS; r++) {
                int sb = row0 + r;
                int w  = widx[sb * NWORD + te];
                sx[r][t0] = embed[w * HD + t0];
            }
        } else if (MODE == 1) {
#pragma unroll
            for (int r = 0; r < ROWS; r++) {
                int rv = row0 + r;
                int sb = rv * SPR + te;
                sx[r][t0] = xin0[sb * HD + t0] + xin1[sb * HD + t0];
            }
        } else {
            for (int k = t0; k < D; k += blockDim.x)
                sx[0][k] = xin0[te * D + k];
        }
        __syncthreads();

        // ---- accumulate gates ----
        float ax0[ROWS], ax1[ROWS], ax2[ROWS];
        float ah0[ROWS], ah1[ROWS], ah2[ROWS];
#pragma unroll
        for (int r = 0; r < ROWS; r++) {
            ax0[r] = ax1[r] = ax2[r] = 0.0f;
            ah0[r] = ah1[r] = ah2[r] = 0.0f;
        }

        for (int k = 0; k < D; k++) {
            const float wi0 = wih[k * GG + t0];
            const float wi1 = wih[k * GG + 256 + t0];
            const float wi2 = wih[k * GG + 512 + t0];
#pragma unroll
            for (int r = 0; r < ROWS; r++) {
                const float xk = sx[r][k];
                ax0[r] += xk * wi0;
                ax1[r] += xk * wi1;
                ax2[r] += xk * wi2;
            }
        }
        for (int k = 0; k < HD; k++) {
            const float wh0 = whh[k * GG + t0];
            const float wh1 = whh[k * GG + 256 + t0];
            const float wh2 = whh[k * GG + 512 + t0];
#pragma unroll
            for (int r = 0; r < ROWS; r++) {
                const float hk = sh[r][k];
                ah0[r] += hk * wh0;
                ah1[r] += hk * wh1;
                ah2[r] += hk * wh2;
            }
        }
        __syncthreads();  // all reads of sh/sx done

        // ---- gates + state update (thread-local hidden dim) ----
#pragma unroll
        for (int r = 0; r < ROWS; r++) {
            const float hold = sh[r][t0];
            const float rg = sigf(ax0[r] + bi0 + ah0[r] + bh0);
            const float zg = sigf(ax1[r] + bi1 + ah1[r] + bh1);
            const float ng = tanhf(ax2[r] + bi2 + rg * (ah2[r] + bh2));
            sh[r][t0] = (1.0f - zg) * ng + zg * hold;
        }
        __syncthreads();
    }

#pragma unroll
    for (int r = 0; r < ROWS; r++) {
        int b = row0 + r;
        out[(dir * nbatch + b) * HD + t0] = sh[r][t0];
    }
}

// ---------------- p_batch = [rev_f + rev_b, normalize(uf)*uf_w] ----------------
__global__ void pbatch_kernel(const float* __restrict__ rev0,
                              const float* __restrict__ rev1,
                              const float* __restrict__ user_feats,
                              const float* __restrict__ uf_w,
                              float* __restrict__ pbatch) {
    int b = blockIdx.x;
    int t = threadIdx.x;  // 288 threads
    if (t < HD) {
        pbatch[b * DREV + t] = rev0[b * HD + t] + rev1[b * HD + t];
    } else {
        int lane = t - HD;  // 0..31 (one full warp)
        float v = (lane < UF) ? user_feats[b * UF + lane] : 0.0f;
        float s = v * v;
#pragma unroll
        for (int o = 16; o > 0; o >>= 1) s += __shfl_xor_sync(0xffffffffu, s, o);
        float nrm = fmaxf(sqrtf(s), 1e-12f);
        if (lane < UF) pbatch[b * DREV + HD + lane] = (v / nrm) * uf_w[lane];
    }
}

// ---------------- r_stars head ----------------
__global__ void rstars_kernel(const float* __restrict__ pbatch,
                              const float* __restrict__ w1, const float* __restrict__ b1,
                              const float* __restrict__ w2, const float* __restrict__ b2,
                              float* __restrict__ out) {
    int b = blockIdx.x;
    int j = threadIdx.x;  // 128
    float s = b1[j];
    for (int k = 0; k < DREV; k++) s += pbatch[b * DREV + k] * w1[j * DREV + k];
    float a = seluf(s) * w2[j];
    __shared__ float red[128];
    red[j] = a;
    __syncthreads();
    for (int st = 64; st > 0; st >>= 1) {
        if (j < st) red[j] += red[j + st];
        __syncthreads();
    }
    if (j == 0) out[9 + b] = red[0] + b2[0];
}

// ---------------- p_stars head ----------------
__global__ void pstars_kernel(const float* __restrict__ doc,
                              const float* __restrict__ w1, const float* __restrict__ b1,
                              const float* __restrict__ w2, const float* __restrict__ b2,
                              float* __restrict__ out) {
    int j = threadIdx.x;  // 128
    __shared__ float hid[128];
    float s = b1[j];
    for (int k = 0; k < HD; k++) s += (doc[k] + doc[HD + k]) * w1[j * HD + k];
    hid[j] = seluf(s);
    __syncthreads();
    if (j < 9) {
        float o = b2[j];
        for (int k = 0; k < 128; k++) o += hid[k] * w2[j * 128 + k];
        out[j] = o;
    }
}

// ---------------- launch ----------------
extern "C" void kernel_launch(void* const* d_in, const int* in_sizes, int n_in,
                              void* d_out, int out_size) {
    (void)in_sizes; (void)n_in; (void)out_size;
    const int*   inputs     = (const int*)d_in[0];
    // d_in[1]=sent_lengths, d_in[2]=sent_counts : unused by reference
    const float* user_feats = (const float*)d_in[3];
    const float* embed      = (const float*)d_in[4];
    const float* wg_wih = (const float*)d_in[5];
    const float* wg_whh = (const float*)d_in[6];
    const float* wg_bih = (const float*)d_in[7];
    const float* wg_bhh = (const float*)d_in[8];
    const float* sg_wih = (const float*)d_in[9];
    const float* sg_whh = (const float*)d_in[10];
    const float* sg_bih = (const float*)d_in[11];
    const float* sg_bhh = (const float*)d_in[12];
    const float* rg_wih = (const float*)d_in[13];
    const float* rg_whh = (const float*)d_in[14];
    const float* rg_bih = (const float*)d_in[15];
    const float* rg_bhh = (const float*)d_in[16];
    const float* rfc_w1 = (const float*)d_in[17];
    const float* rfc_b1 = (const float*)d_in[18];
    const float* rfc_w2 = (const float*)d_in[19];
    const float* rfc_b2 = (const float*)d_in[20];
    const float* pfc_w1 = (const float*)d_in[21];
    const float* pfc_b1 = (const float*)d_in[22];
    const float* pfc_w2 = (const float*)d_in[23];
    const float* pfc_b2 = (const float*)d_in[24];
    const float* uf_w   = (const float*)d_in[25];
    float* out = (float*)d_out;

    float *wgTih, *wgThh, *sgTih, *sgThh, *rgTih, *rgThh;
    float *sent, *rev, *pbatch, *doc;
    cudaGetSymbolAddress((void**)&wgTih, g_wgT_ih);
    cudaGetSymbolAddress((void**)&wgThh, g_wgT_hh);
    cudaGetSymbolAddress((void**)&sgTih, g_sgT_ih);
    cudaGetSymbolAddress((void**)&sgThh, g_sgT_hh);
    cudaGetSymbolAddress((void**)&rgTih, g_rgT_ih);
    cudaGetSymbolAddress((void**)&rgThh, g_rgT_hh);
    cudaGetSymbolAddress((void**)&sent,  g_sent);
    cudaGetSymbolAddress((void**)&rev,   g_rev);
    cudaGetSymbolAddress((void**)&pbatch,g_pbatch);
    cudaGetSymbolAddress((void**)&doc,   g_doc);

    // 1. transpose all GRU weights to [dir][K][768] for coalesced loads
    {
        int tot, nb;
        tot = 2 * GG * 256; nb = (tot + 255) / 256;
        transpose_kernel<<<nb, 256>>>(wg_wih, wgTih, 256);
        transpose_kernel<<<nb, 256>>>(wg_whh, wgThh, 256);
        transpose_kernel<<<nb, 256>>>(sg_wih, sgTih, 256);
        transpose_kernel<<<nb, 256>>>(sg_whh, sgThh, 256);
        transpose_kernel<<<nb, 256>>>(rg_whh, rgThh, 256);
        tot = 2 * GG * DREV; nb = (tot + 255) / 256;
        transpose_kernel<<<nb, 256>>>(rg_wih, rgTih, DREV);
    }

    // 2. word-level bi-GRU: 2048 sentences, T=64, D=256
    gru_kernel<0, 8, NWORD, 256><<<dim3(NSENT / 8, 2), 256>>>(
        inputs, embed, nullptr, nullptr,
        wgTih, wgThh, wg_bih, wg_bhh, sent, NSENT);

    // 3. sentence-level bi-GRU: 64 reviews, T=32, D=256
    gru_kernel<1, 2, SPR, 256><<<dim3(NREV / 2, 2), 256>>>(
        nullptr, nullptr, sent, sent + NSENT * HD,
        sgTih, sgThh, sg_bih, sg_bhh, rev, NREV);

    // 4. p_batch = [rev_f+rev_b, normalize(user_feats)*uf_w]
    pbatch_kernel<<<NREV, 288>>>(rev, rev + NREV * HD, user_feats, uf_w, pbatch);

    // 5. r_stars head -> out[9..73)
    rstars_kernel<<<NREV, 128>>>(pbatch, rfc_w1, rfc_b1, rfc_w2, rfc_b2, out);

    // 6. review-level bi-GRU: batch 1, T=64, D=276
    gru_kernel<2, 1, NREV, DREV><<<dim3(1, 2), 256>>>(
        nullptr, nullptr, pbatch, nullptr,
        rgTih, rgThh, rg_bih, rg_bhh, doc, 1);

    // 7. p_stars head -> out[0..9)
    pstars_kernel<<<1, 128>>>(doc, pfc_w1, pfc_b1, pfc_w2, pfc_b2, out);
}

// round 3
// speedup vs baseline: 2.0797x; 2.0797x over previous
#include <cuda_runtime.h>
#include <math.h>

// Problem constants
#define HD 256          // hidden dim
#define GG 768          // 3*H gates
#define NSENT 2048      // R*S sentences
#define NWORD 64        // words per sentence
#define NREV 64         // reviews
#define SPR 32          // sentences per review
#define DREV 276        // H + UF
#define UF 20
#define NTOK_W (NSENT * NWORD)   // 131072 word tokens

typedef unsigned long long u64;

// ---------------- scratch (static device arrays; no allocation allowed) ----------------
__device__ float g_wgT_ih[2 * 256 * GG];
__device__ float g_wgT_hh[2 * 256 * GG];
__device__ float g_sgT_ih[2 * 256 * GG];
__device__ float g_sgT_hh[2 * 256 * GG];
__device__ float g_rgT_ih[2 * DREV * GG];
__device__ float g_rgT_hh[2 * 256 * GG];
__device__ float g_gx_w[(size_t)2 * NTOK_W * GG];  // word input-gates (805 MB)
__device__ float g_gx_s[2 * NSENT * GG];           // sentence input-gates
__device__ float g_gx_r[2 * NREV * GG];            // review input-gates
__device__ float g_sent[2 * NSENT * HD];
__device__ float g_rev[2 * NREV * HD];
__device__ float g_pbatch[NREV * DREV];
__device__ float g_doc[2 * HD];

// ---------------- helpers ----------------
__device__ __forceinline__ float sigf(float x) { return 1.0f / (1.0f + __expf(-x)); }

__device__ __forceinline__ float seluf(float x) {
    const float alpha = 1.6732632423543772f;
    const float scale = 1.0507009873554805f;
    return x > 0.0f ? scale * x : scale * alpha * (expf(x) - 1.0f);
}

__device__ __forceinline__ u64 pack2(float lo, float hi) {
    u64 r; asm("mov.b64 %0, {%1, %2};" : "=l"(r) : "f"(lo), "f"(hi)); return r;
}
__device__ __forceinline__ void unpack2(u64 v, float& lo, float& hi) {
    asm("mov.b64 {%0, %1}, %2;" : "=f"(lo), "=f"(hi) : "l"(v));
}
// packed dual fp32 FMA: d.lo = a.lo*b.lo + c.lo ; d.hi = a.hi*b.hi + c.hi
__device__ __forceinline__ u64 fma2(u64 a, u64 b, u64 c) {
    u64 d; asm("fma.rn.f32x2 %0, %1, %2, %3;" : "=l"(d) : "l"(a), "l"(b), "l"(c)); return d;
}

// ---------------- weight transpose: src [2][768][Din] -> dst [2][Din][768] ----------------
__global__ void transpose_kernel(const float* __restrict__ src, float* __restrict__ dst, int Din) {
    int idx = blockIdx.x * blockDim.x + threadIdx.x;
    int total = 2 * GG * Din;
    if (idx >= total) return;
    int g = idx % GG;
    int rem = idx / GG;
    int k = rem % Din;
    int d = rem / Din;
    dst[idx] = src[(d * GG + g) * Din + k];
}

// ---------------- input-gates GEMM: gx[dir][tok][768] = x @ WihT + bih ----------------
// MODE 0: x = embed[widx[tok]]   (word level)
// MODE 1: x = xin0[tok] + xin1[tok]  (sentence level, fwd+bwd word states)
// MODE 2: x = xin0[tok]  (review level, p_batch rows, K=276)
template <int MODE, int K, int TOKS>
__global__ __launch_bounds__(256, 2)
void gates_gemm_kernel(const int* __restrict__ widx,
                       const float* __restrict__ embed,
                       const float* __restrict__ xin0,
                       const float* __restrict__ xin1,
                       const float* __restrict__ wT_ih,
                       const float* __restrict__ bih,
                       float* __restrict__ gx, int M) {
    constexpr int P = TOKS / 2;
    const int dir  = blockIdx.y;
    const int tok0 = blockIdx.x * TOKS;
    const int t0   = threadIdx.x;

    __shared__ float2 sx2[K][P];

    // stage x pairs into shared memory (once per block; no time loop here)
#pragma unroll
    for (int p = 0; p < P; p++) {
        const int ta = tok0 + 2 * p, tb = ta + 1;
        for (int k = t0; k < K; k += 256) {
            float xa, xb;
            if (MODE == 0) {
                xa = embed[(size_t)widx[ta] * HD + k];
                xb = embed[(size_t)widx[tb] * HD + k];
            } else if (MODE == 1) {
                xa = xin0[(size_t)ta * HD + k] + xin1[(size_t)ta * HD + k];
                xb = xin0[(size_t)tb * HD + k] + xin1[(size_t)tb * HD + k];
            } else {
                xa = xin0[(size_t)ta * K + k];
                xb = xin0[(size_t)tb * K + k];
            }
            sx2[k][p] = make_float2(xa, xb);
        }
    }
    __syncthreads();

    const float* wih = wT_ih + (size_t)dir * K * GG;
    u64 acc[P][3];
#pragma unroll
    for (int p = 0; p < P; p++) acc[p][0] = acc[p][1] = acc[p][2] = 0ull;

#pragma unroll 4
    for (int k = 0; k < K; k++) {
        const float w0 = wih[(size_t)k * GG + t0];
        const float w1 = wih[(size_t)k * GG + 256 + t0];
        const float w2 = wih[(size_t)k * GG + 512 + t0];
        const u64 w0p = pack2(w0, w0), w1p = pack2(w1, w1), w2p = pack2(w2, w2);
#pragma unroll
        for (int p = 0; p < P; p++) {
            const u64 xp = *reinterpret_cast<const u64*>(&sx2[k][p]);
            acc[p][0] = fma2(xp, w0p, acc[p][0]);
            acc[p][1] = fma2(xp, w1p, acc[p][1]);
            acc[p][2] = fma2(xp, w2p, acc[p][2]);
        }
    }

    const float bi0 = bih[dir * GG + t0];
    const float bi1 = bih[dir * GG + 256 + t0];
    const float bi2 = bih[dir * GG + 512 + t0];
#pragma unroll
    for (int p = 0; p < P; p++) {
        float a0, b0, a1, b1, a2, b2;
        unpack2(acc[p][0], a0, b0);
        unpack2(acc[p][1], a1, b1);
        unpack2(acc[p][2], a2, b2);
        float* oa = gx + ((size_t)dir * M + tok0 + 2 * p) * GG;
        float* ob = oa + GG;
        oa[t0]       = a0 + bi0;  ob[t0]       = b0 + bi0;
        oa[256 + t0] = a1 + bi1;  ob[256 + t0] = b1 + bi1;
        oa[512 + t0] = a2 + bi2;  ob[512 + t0] = b2 + bi2;
    }
}

// ---------------- recurrent GRU (input gates precomputed), row-paired f32x2 ----------------
// gx[dir][row*T + t][768] already includes bih. Thread t0 owns gates {t0,t0+256,t0+512}
// and hidden dim t0. ROWS must be even; pairs share packed f32x2 lanes.
template <int ROWS, int T>
__global__ __launch_bounds__(256, 2)
void gru_rec_kernel(const float* __restrict__ gx,
                    const float* __restrict__ wT_hh,
                    const float* __restrict__ bhh,
                    float* __restrict__ out, int nbatch) {
    constexpr int P = ROWS / 2;
    const int dir  = blockIdx.y;
    const int row0 = blockIdx.x * ROWS;
    const int t0   = threadIdx.x;

    __shared__ float2 sh2[HD][P];
#pragma unroll
    for (int p = 0; p < P; p++) sh2[t0][p] = make_float2(0.0f, 0.0f);

    const float* whh = wT_hh + (size_t)dir * HD * GG;
    const float bh0 = bhh[dir * GG + t0];
    const float bh1 = bhh[dir * GG + 256 + t0];
    const float bh2 = bhh[dir * GG + 512 + t0];
    const size_t Mtok = (size_t)nbatch * T;
    __syncthreads();

    for (int t = 0; t < T; t++) {
        const int te = dir ? (T - 1 - t) : t;

        u64 ax[P][3], ah[P][3];
#pragma unroll
        for (int p = 0; p < P; p++) {
            const float* ga = gx + ((size_t)dir * Mtok + (size_t)(row0 + 2 * p) * T + te) * GG;
            const float* gb = ga + (size_t)T * GG;
            ax[p][0] = pack2(ga[t0],       gb[t0]);
            ax[p][1] = pack2(ga[256 + t0], gb[256 + t0]);
            ax[p][2] = pack2(ga[512 + t0], gb[512 + t0]);
            ah[p][0] = ah[p][1] = ah[p][2] = 0ull;
        }

#pragma unroll 4
        for (int k = 0; k < HD; k++) {
            const float w0 = whh[(size_t)k * GG + t0];
            const float w1 = whh[(size_t)k * GG + 256 + t0];
            const float w2 = whh[(size_t)k * GG + 512 + t0];
            const u64 w0p = pack2(w0, w0), w1p = pack2(w1, w1), w2p = pack2(w2, w2);
#pragma unroll
            for (int p = 0; p < P; p++) {
                const u64 hp = *reinterpret_cast<const u64*>(&sh2[k][p]);
                ah[p][0] = fma2(hp, w0p, ah[p][0]);
                ah[p][1] = fma2(hp, w1p, ah[p][1]);
                ah[p][2] = fma2(hp, w2p, ah[p][2]);
            }
        }
        __syncthreads();  // all reads of sh2 done before writes

#pragma unroll
        for (int p = 0; p < P; p++) {
            float x0a, x0b, x1a, x1b, x2a, x2b;
            float h0a, h0b, h1a, h1b, h2a, h2b;
            unpack2(ax[p][0], x0a, x0b); unpack2(ax[p][1], x1a, x1b); unpack2(ax[p][2], x2a, x2b);
            unpack2(ah[p][0], h0a, h0b); unpack2(ah[p][1], h1a, h1b); unpack2(ah[p][2], h2a, h2b);
            const float2 hold = sh2[t0][p];
            const float ra = sigf(x0a + h0a + bh0), rb = sigf(x0b + h0b + bh0);
            const float za = sigf(x1a + h1a + bh1), zb = sigf(x1b + h1b + bh1);
            const float na = tanhf(x2a + ra * (h2a + bh2));
            const float nb = tanhf(x2b + rb * (h2b + bh2));
            sh2[t0][p] = make_float2((1.0f - za) * na + za * hold.x,
                                     (1.0f - zb) * nb + zb * hold.y);
        }
        __syncthreads();
    }

#pragma unroll
    for (int p = 0; p < P; p++) {
        const float2 h = sh2[t0][p];
        out[((size_t)dir * nbatch + row0 + 2 * p) * HD + t0]     = h.x;
        out[((size_t)dir * nbatch + row0 + 2 * p + 1) * HD + t0] = h.y;
    }
}

// ---------------- review-level recurrent GRU (batch 1, scalar) ----------------
__global__ void gru_rec1_kernel(const float* __restrict__ gx,
                                const float* __restrict__ wT_hh,
                                const float* __restrict__ bhh,
                                float* __restrict__ out) {
    const int dir = blockIdx.x;
    const int t0  = threadIdx.x;
    __shared__ float sh[HD];
    sh[t0] = 0.0f;
    const float* whh = wT_hh + (size_t)dir * HD * GG;
    const float bh0 = bhh[dir * GG + t0];
    const float bh1 = bhh[dir * GG + 256 + t0];
    const float bh2 = bhh[dir * GG + 512 + t0];
    __syncthreads();

    for (int t = 0; t < NREV; t++) {
        const int te = dir ? (NREV - 1 - t) : t;
        const float* ga = gx + ((size_t)dir * NREV + te) * GG;
        const float x0 = ga[t0], x1 = ga[256 + t0], x2 = ga[512 + t0];
        float a0 = 0.0f, a1 = 0.0f, a2 = 0.0f;
#pragma unroll 4
        for (int k = 0; k < HD; k++) {
            const float hk = sh[k];
            a0 += hk * whh[(size_t)k * GG + t0];
            a1 += hk * whh[(size_t)k * GG + 256 + t0];
            a2 += hk * whh[(size_t)k * GG + 512 + t0];
        }
        const float hold = sh[t0];
        __syncthreads();
        const float r = sigf(x0 + a0 + bh0);
        const float z = sigf(x1 + a1 + bh1);
        const float n = tanhf(x2 + r * (a2 + bh2));
        sh[t0] = (1.0f - z) * n + z * hold;
        __syncthreads();
    }
    out[dir * HD + t0] = sh[t0];
}

// ---------------- p_batch = [rev_f + rev_b, normalize(uf)*uf_w] ----------------
__global__ void pbatch_kernel(const float* __restrict__ rev0,
                              const float* __restrict__ rev1,
                              const float* __restrict__ user_feats,
                              const float* __restrict__ uf_w,
                              float* __restrict__ pbatch) {
    int b = blockIdx.x;
    int t = threadIdx.x;  // 288 threads
    if (t < HD) {
        pbatch[b * DREV + t] = rev0[b * HD + t] + rev1[b * HD + t];
    } else {
        int lane = t - HD;  // one full warp
        float v = (lane < UF) ? user_feats[b * UF + lane] : 0.0f;
        float s = v * v;
#pragma unroll
        for (int o = 16; o > 0; o >>= 1) s += __shfl_xor_sync(0xffffffffu, s, o);
        float nrm = fmaxf(sqrtf(s), 1e-12f);
        if (lane < UF) pbatch[b * DREV + HD + lane] = (v / nrm) * uf_w[lane];
    }
}

// ---------------- r_stars head ----------------
__global__ void rstars_kernel(const float* __restrict__ pbatch,
                              const float* __restrict__ w1, const float* __restrict__ b1,
                              const float* __restrict__ w2, const float* __restrict__ b2,
                              float* __restrict__ out) {
    int b = blockIdx.x;
    int j = threadIdx.x;  // 128
    float s = b1[j];
    for (int k = 0; k < DREV; k++) s += pbatch[b * DREV + k] * w1[j * DREV + k];
    float a = seluf(s) * w2[j];
    __shared__ float red[128];
    red[j] = a;
    __syncthreads();
    for (int st = 64; st > 0; st >>= 1) {
        if (j < st) red[j] += red[j + st];
        __syncthreads();
    }
    if (j == 0) out[9 + b] = red[0] + b2[0];
}

// ---------------- p_stars head ----------------
__global__ void pstars_kernel(const float* __restrict__ doc,
                              const float* __restrict__ w1, const float* __restrict__ b1,
                              const float* __restrict__ w2, const float* __restrict__ b2,
                              float* __restrict__ out) {
    int j = threadIdx.x;  // 128
    __shared__ float hid[128];
    float s = b1[j];
    for (int k = 0; k < HD; k++) s += (doc[k] + doc[HD + k]) * w1[j * HD + k];
    hid[j] = seluf(s);
    __syncthreads();
    if (j < 9) {
        float o = b2[j];
        for (int k = 0; k < 128; k++) o += hid[k] * w2[j * 128 + k];
        out[j] = o;
    }
}

// ---------------- launch ----------------
extern "C" void kernel_launch(void* const* d_in, const int* in_sizes, int n_in,
                              void* d_out, int out_size) {
    (void)in_sizes; (void)n_in; (void)out_size;
    const int*   inputs     = (const int*)d_in[0];
    // d_in[1]=sent_lengths, d_in[2]=sent_counts : unused by reference
    const float* user_feats = (const float*)d_in[3];
    const float* embed      = (const float*)d_in[4];
    const float* wg_wih = (const float*)d_in[5];
    const float* wg_whh = (const float*)d_in[6];
    const float* wg_bih = (const float*)d_in[7];
    const float* wg_bhh = (const float*)d_in[8];
    const float* sg_wih = (const float*)d_in[9];
    const float* sg_whh = (const float*)d_in[10];
    const float* sg_bih = (const float*)d_in[11];
    const float* sg_bhh = (const float*)d_in[12];
    const float* rg_wih = (const float*)d_in[13];
    const float* rg_whh = (const float*)d_in[14];
    const float* rg_bih = (const float*)d_in[15];
    const float* rg_bhh = (const float*)d_in[16];
    const float* rfc_w1 = (const float*)d_in[17];
    const float* rfc_b1 = (const float*)d_in[18];
    const float* rfc_w2 = (const float*)d_in[19];
    const float* rfc_b2 = (const float*)d_in[20];
    const float* pfc_w1 = (const float*)d_in[21];
    const float* pfc_b1 = (const float*)d_in[22];
    const float* pfc_w2 = (const float*)d_in[23];
    const float* pfc_b2 = (const float*)d_in[24];
    const float* uf_w   = (const float*)d_in[25];
    float* out = (float*)d_out;

    float *wgTih, *wgThh, *sgTih, *sgThh, *rgTih, *rgThh;
    float *gxw, *gxs, *gxr, *sent, *rev, *pbatch, *doc;
    cudaGetSymbolAddress((void**)&wgTih, g_wgT_ih);
    cudaGetSymbolAddress((void**)&wgThh, g_wgT_hh);
    cudaGetSymbolAddress((void**)&sgTih, g_sgT_ih);
    cudaGetSymbolAddress((void**)&sgThh, g_sgT_hh);
    cudaGetSymbolAddress((void**)&rgTih, g_rgT_ih);
    cudaGetSymbolAddress((void**)&rgThh, g_rgT_hh);
    cudaGetSymbolAddress((void**)&gxw,   g_gx_w);
    cudaGetSymbolAddress((void**)&gxs,   g_gx_s);
    cudaGetSymbolAddress((void**)&gxr,   g_gx_r);
    cudaGetSymbolAddress((void**)&sent,  g_sent);
    cudaGetSymbolAddress((void**)&rev,   g_rev);
    cudaGetSymbolAddress((void**)&pbatch,g_pbatch);
    cudaGetSymbolAddress((void**)&doc,   g_doc);

    // 1. transpose all GRU weights to [dir][K][768]
    {
        int tot, nb;
        tot = 2 * GG * 256; nb = (tot + 255) / 256;
        transpose_kernel<<<nb, 256>>>(wg_wih, wgTih, 256);
        transpose_kernel<<<nb, 256>>>(wg_whh, wgThh, 256);
        transpose_kernel<<<nb, 256>>>(sg_wih, sgTih, 256);
        transpose_kernel<<<nb, 256>>>(sg_whh, sgThh, 256);
        transpose_kernel<<<nb, 256>>>(rg_whh, rgThh, 256);
        tot = 2 * GG * DREV; nb = (tot + 255) / 256;
        transpose_kernel<<<nb, 256>>>(rg_wih, rgTih, DREV);
    }

    // 2. word level: input-gate GEMM over all 131072 tokens, then recurrent pass
    gates_gemm_kernel<0, 256, 16><<<dim3(NTOK_W / 16, 2), 256>>>(
        inputs, embed, nullptr, nullptr, wgTih, wg_bih, gxw, NTOK_W);
    gru_rec_kernel<16, NWORD><<<dim3(NSENT / 16, 2), 256>>>(
        gxw, wgThh, wg_bhh, sent, NSENT);

    // 3. sentence level
    gates_gemm_kernel<1, 256, 16><<<dim3(NSENT / 16, 2), 256>>>(
        nullptr, nullptr, sent, sent + NSENT * HD, sgTih, sg_bih, gxs, NSENT);
    gru_rec_kernel<2, SPR><<<dim3(NREV / 2, 2), 256>>>(
        gxs, sgThh, sg_bhh, rev, NREV);

    // 4. p_batch = [rev_f+rev_b, normalize(user_feats)*uf_w]
    pbatch_kernel<<<NREV, 288>>>(rev, rev + NREV * HD, user_feats, uf_w, pbatch);

    // 5. r_stars head -> out[9..73)
    rstars_kernel<<<NREV, 128>>>(pbatch, rfc_w1, rfc_b1, rfc_w2, rfc_b2, out);

    // 6. review level: input-gate GEMM then batch-1 recurrent pass
    gates_gemm_kernel<2, DREV, 16><<<dim3(NREV / 16, 2), 256>>>(
        nullptr, nullptr, pbatch, nullptr, rgTih, rg_bih, gxr, NREV);
    gru_rec1_kernel<<<2, 256>>>(gxr, rgThh, rg_bhh, doc);

    // 7. p_stars head -> out[0..9)
    pstars_kernel<<<1, 128>>>(doc, pfc_w1, pfc_b1, pfc_w2, pfc_b2, out);
}

// round 4
// speedup vs baseline: 2.2345x; 1.0744x over previous
#include <cuda_runtime.h>
#include <math.h>

// Problem constants
#define HD 256          // hidden dim
#define GG 768          // 3*H gates
#define NSENT 2048      // R*S sentences
#define NWORD 64        // words per sentence
#define NREV 64         // reviews
#define SPR 32          // sentences per review
#define DREV 276        // H + UF
#define DREVP 288       // padded to multiple of 16
#define UF 20
#define NTOK_W (NSENT * NWORD)   // 131072 word tokens

typedef unsigned long long u64;

// ---------------- scratch (static device arrays; no allocation allowed) ----------------
__device__ float g_wgT_ih[2 * 256 * GG];
__device__ float g_wgT_hh[2 * 256 * GG];
__device__ float g_sgT_ih[2 * 256 * GG];
__device__ float g_sgT_hh[2 * 256 * GG];
__device__ float g_rgT_ih[2 * DREVP * GG];
__device__ float g_rgT_hh[2 * 256 * GG];
__device__ float g_gx_w[(size_t)2 * NTOK_W * GG];  // word input-gates (805 MB)
__device__ float g_gx_s[2 * NSENT * GG];           // sentence input-gates
__device__ float g_gx_r[2 * NREV * GG];            // review input-gates
__device__ float g_sent[2 * NSENT * HD];
__device__ float g_rev[2 * NREV * HD];
__device__ float g_pbatch[NREV * DREV];
__device__ float g_doc[2 * HD];

// ---------------- helpers ----------------
__device__ __forceinline__ float sigf(float x) { return 1.0f / (1.0f + __expf(-x)); }

__device__ __forceinline__ float seluf(float x) {
    const float alpha = 1.6732632423543772f;
    const float scale = 1.0507009873554805f;
    return x > 0.0f ? scale * x : scale * alpha * (expf(x) - 1.0f);
}

__device__ __forceinline__ u64 pack2(float lo, float hi) {
    u64 r; asm("mov.b64 %0, {%1, %2};" : "=l"(r) : "f"(lo), "f"(hi)); return r;
}
__device__ __forceinline__ void unpack2(u64 v, float& lo, float& hi) {
    asm("mov.b64 {%0, %1}, %2;" : "=f"(lo), "=f"(hi) : "l"(v));
}
// packed dual fp32 FMA: d.lo = a.lo*b.lo + c.lo ; d.hi = a.hi*b.hi + c.hi
__device__ __forceinline__ u64 fma2(u64 a, u64 b, u64 c) {
    u64 d; asm("fma.rn.f32x2 %0, %1, %2, %3;" : "=l"(d) : "l"(a), "l"(b), "l"(c)); return d;
}

// prefetch U consecutive k-rows of the 3 gate columns owned by this thread
template <int U>
__device__ __forceinline__ void load_wchunk(float (&w)[3][U], const float* __restrict__ base, int kb) {
#pragma unroll
    for (int u = 0; u < U; u++) {
        const float* p = base + (size_t)(kb + u) * GG;
        w[0][u] = __ldg(p);
        w[1][u] = __ldg(p + 256);
        w[2][u] = __ldg(p + 512);
    }
}

// FMA2 chunk: acc[p][g] += x2[p][kb+u] * (w[g][u], w[g][u])
template <int U, int P, int K>
__device__ __forceinline__ void fma_chunk(u64 (&acc)[P][3], const float (&w)[3][U],
                                          const float2 (*sx)[K], int kb) {
#pragma unroll
    for (int u = 0; u < U; u++) {
        const u64 w0p = pack2(w[0][u], w[0][u]);
        const u64 w1p = pack2(w[1][u], w[1][u]);
        const u64 w2p = pack2(w[2][u], w[2][u]);
#pragma unroll
        for (int p = 0; p < P; p++) {
            const u64 xp = *reinterpret_cast<const u64*>(&sx[p][kb + u]);
            acc[p][0] = fma2(xp, w0p, acc[p][0]);
            acc[p][1] = fma2(xp, w1p, acc[p][1]);
            acc[p][2] = fma2(xp, w2p, acc[p][2]);
        }
    }
}

// ---------------- weight transpose: src [2][768][Din] -> dst [2][Dpad][768] ----------------
__global__ void transpose_kernel(const float* __restrict__ src, float* __restrict__ dst,
                                 int Din, int Dpad) {
    int idx = blockIdx.x * blockDim.x + threadIdx.x;
    int total = 2 * GG * Din;
    if (idx >= total) return;
    int g = idx % GG;
    int rem = idx / GG;
    int k = rem % Din;
    int d = rem / Din;
    dst[((size_t)d * Dpad + k) * GG + g] = src[((size_t)d * GG + g) * Din + k];
}

// ---------------- input-gates GEMM: gx[dir][tok][768] = x @ WihT + bih ----------------
// MODE 0: x = embed[widx[tok]]   (word level)
// MODE 1: x = xin0[tok] + xin1[tok]  (sentence level, fwd+bwd word states)
// MODE 2: x = xin0[tok]  (review level, p_batch rows, true K = KD, padded to K)
template <int MODE, int K, int KD, int TOKS>
__global__ __launch_bounds__(256)
void gates_gemm_kernel(const int* __restrict__ widx,
                       const float* __restrict__ embed,
                       const float* __restrict__ xin0,
                       const float* __restrict__ xin1,
                       const float* __restrict__ wT_ih,
                       const float* __restrict__ bih,
                       float* __restrict__ gx, int M) {
    constexpr int P = TOKS / 2;
    constexpr int U = 8;
    const int dir  = blockIdx.y;
    const int tok0 = blockIdx.x * TOKS;
    const int t0   = threadIdx.x;

    __shared__ float2 sx2[P][K];   // [pair][k] so k is contiguous

    // stage x pairs into shared memory (once per block)
#pragma unroll
    for (int p = 0; p < P; p++) {
        const int ta = tok0 + 2 * p, tb = ta + 1;
        for (int k = t0; k < K; k += 256) {
            float xa, xb;
            if (MODE == 0) {
                xa = embed[(size_t)widx[ta] * HD + k];
                xb = embed[(size_t)widx[tb] * HD + k];
            } else if (MODE == 1) {
                xa = xin0[(size_t)ta * HD + k] + xin1[(size_t)ta * HD + k];
                xb = xin0[(size_t)tb * HD + k] + xin1[(size_t)tb * HD + k];
            } else {
                xa = (k < KD) ? xin0[(size_t)ta * KD + k] : 0.0f;
                xb = (k < KD) ? xin0[(size_t)tb * KD + k] : 0.0f;
            }
            sx2[p][k] = make_float2(xa, xb);
        }
    }
    __syncthreads();

    const float* wbase = wT_ih + (size_t)dir * K * GG + t0;
    u64 acc[P][3];
#pragma unroll
    for (int p = 0; p < P; p++) acc[p][0] = acc[p][1] = acc[p][2] = 0ull;

    float wA[3][U], wB[3][U];
    load_wchunk<U>(wA, wbase, 0);
#pragma unroll 1
    for (int kb = 0; kb < K; kb += 2 * U) {
        load_wchunk<U>(wB, wbase, kb + U);
        fma_chunk<U, P, K>(acc, wA, sx2, kb);
        if (kb + 2 * U < K) load_wchunk<U>(wA, wbase, kb + 2 * U);
        fma_chunk<U, P, K>(acc, wB, sx2, kb + U);
    }

    const float bi0 = bih[dir * GG + t0];
    const float bi1 = bih[dir * GG + 256 + t0];
    const float bi2 = bih[dir * GG + 512 + t0];
#pragma unroll
    for (int p = 0; p < P; p++) {
        float a0, b0, a1, b1, a2, b2;
        unpack2(acc[p][0], a0, b0);
        unpack2(acc[p][1], a1, b1);
        unpack2(acc[p][2], a2, b2);
        float* oa = gx + ((size_t)dir * M + tok0 + 2 * p) * GG;
        float* ob = oa + GG;
        oa[t0]       = a0 + bi0;  ob[t0]       = b0 + bi0;
        oa[256 + t0] = a1 + bi1;  ob[256 + t0] = b1 + bi1;
        oa[512 + t0] = a2 + bi2;  ob[512 + t0] = b2 + bi2;
    }
}

// ---------------- recurrent GRU (input gates precomputed), row-paired f32x2 ----------------
template <int ROWS, int T>
__global__ __launch_bounds__(256)
void gru_rec_kernel(const float* __restrict__ gx,
                    const float* __restrict__ wT_hh,
                    const float* __restrict__ bhh,
                    float* __restrict__ out, int nbatch) {
    constexpr int P = ROWS / 2;
    constexpr int U = 8;
    const int dir  = blockIdx.y;
    const int row0 = blockIdx.x * ROWS;
    const int t0   = threadIdx.x;

    __shared__ float2 sh2[P][HD];   // [pair][k]
#pragma unroll
    for (int p = 0; p < P; p++) sh2[p][t0] = make_float2(0.0f, 0.0f);

    const float* wbase = wT_hh + (size_t)dir * HD * GG + t0;
    const float bh0 = bhh[dir * GG + t0];
    const float bh1 = bhh[dir * GG + 256 + t0];
    const float bh2 = bhh[dir * GG + 512 + t0];
    const size_t Mtok = (size_t)nbatch * T;
    __syncthreads();

    for (int t = 0; t < T; t++) {
        const int te = dir ? (T - 1 - t) : t;

        u64 ax[P][3], ah[P][3];
#pragma unroll
        for (int p = 0; p < P; p++) {
            const float* ga = gx + ((size_t)dir * Mtok + (size_t)(row0 + 2 * p) * T + te) * GG;
            const float* gb = ga + (size_t)T * GG;
            ax[p][0] = pack2(ga[t0],       gb[t0]);
            ax[p][1] = pack2(ga[256 + t0], gb[256 + t0]);
            ax[p][2] = pack2(ga[512 + t0], gb[512 + t0]);
            ah[p][0] = ah[p][1] = ah[p][2] = 0ull;
        }

        float wA[3][U], wB[3][U];
        load_wchunk<U>(wA, wbase, 0);
#pragma unroll 1
        for (int kb = 0; kb < HD; kb += 2 * U) {
            load_wchunk<U>(wB, wbase, kb + U);
            fma_chunk<U, P, HD>(ah, wA, sh2, kb);
            if (kb + 2 * U < HD) load_wchunk<U>(wA, wbase, kb + 2 * U);
            fma_chunk<U, P, HD>(ah, wB, sh2, kb + U);
        }
        __syncthreads();  // all reads of sh2 done before writes

#pragma unroll
        for (int p = 0; p < P; p++) {
            float x0a, x0b, x1a, x1b, x2a, x2b;
            float h0a, h0b, h1a, h1b, h2a, h2b;
            unpack2(ax[p][0], x0a, x0b); unpack2(ax[p][1], x1a, x1b); unpack2(ax[p][2], x2a, x2b);
            unpack2(ah[p][0], h0a, h0b); unpack2(ah[p][1], h1a, h1b); unpack2(ah[p][2], h2a, h2b);
            const float2 hold = sh2[p][t0];
            const float ra = sigf(x0a + h0a + bh0), rb = sigf(x0b + h0b + bh0);
            const float za = sigf(x1a + h1a + bh1), zb = sigf(x1b + h1b + bh1);
            const float na = tanhf(x2a + ra * (h2a + bh2));
            const float nb = tanhf(x2b + rb * (h2b + bh2));
            sh2[p][t0] = make_float2((1.0f - za) * na + za * hold.x,
                                     (1.0f - zb) * nb + zb * hold.y);
        }
        __syncthreads();
    }

#pragma unroll
    for (int p = 0; p < P; p++) {
        const float2 h = sh2[p][t0];
        out[((size_t)dir * nbatch + row0 + 2 * p) * HD + t0]     = h.x;
        out[((size_t)dir * nbatch + row0 + 2 * p + 1) * HD + t0] = h.y;
    }
}

// ---------------- review-level recurrent GRU (batch 1, scalar) ----------------
__global__ void gru_rec1_kernel(const float* __restrict__ gx,
                                const float* __restrict__ wT_hh,
                                const float* __restrict__ bhh,
                                float* __restrict__ out) {
    const int dir = blockIdx.x;
    const int t0  = threadIdx.x;
    __shared__ float sh[HD];
    sh[t0] = 0.0f;
    const float* whh = wT_hh + (size_t)dir * HD * GG;
    const float bh0 = bhh[dir * GG + t0];
    const float bh1 = bhh[dir * GG + 256 + t0];
    const float bh2 = bhh[dir * GG + 512 + t0];
    __syncthreads();

    for (int t = 0; t < NREV; t++) {
        const int te = dir ? (NREV - 1 - t) : t;
        const float* ga = gx + ((size_t)dir * NREV + te) * GG;
        const float x0 = ga[t0], x1 = ga[256 + t0], x2 = ga[512 + t0];
        float a0 = 0.0f, a1 = 0.0f, a2 = 0.0f;
#pragma unroll 8
        for (int k = 0; k < HD; k++) {
            const float hk = sh[k];
            a0 += hk * whh[(size_t)k * GG + t0];
            a1 += hk * whh[(size_t)k * GG + 256 + t0];
            a2 += hk * whh[(size_t)k * GG + 512 + t0];
        }
        const float hold = sh[t0];
        __syncthreads();
        const float r = sigf(x0 + a0 + bh0);
        const float z = sigf(x1 + a1 + bh1);
        const float n = tanhf(x2 + r * (a2 + bh2));
        sh[t0] = (1.0f - z) * n + z * hold;
        __syncthreads();
    }
    out[dir * HD + t0] = sh[t0];
}

// ---------------- p_batch = [rev_f + rev_b, normalize(uf)*uf_w] ----------------
__global__ void pbatch_kernel(const float* __restrict__ rev0,
                              const float* __restrict__ rev1,
                              const float* __restrict__ user_feats,
                              const float* __restrict__ uf_w,
                              float* __restrict__ pbatch) {
    int b = blockIdx.x;
    int t = threadIdx.x;  // 288 threads
    if (t < HD) {
        pbatch[b * DREV + t] = rev0[b * HD + t] + rev1[b * HD + t];
    } else {
        int lane = t - HD;  // one full warp
        float v = (lane < UF) ? user_feats[b * UF + lane] : 0.0f;
        float s = v * v;
#pragma unroll
        for (int o = 16; o > 0; o >>= 1) s += __shfl_xor_sync(0xffffffffu, s, o);
        float nrm = fmaxf(sqrtf(s), 1e-12f);
        if (lane < UF) pbatch[b * DREV + HD + lane] = (v / nrm) * uf_w[lane];
    }
}

// ---------------- r_stars head ----------------
__global__ void rstars_kernel(const float* __restrict__ pbatch,
                              const float* __restrict__ w1, const float* __restrict__ b1,
                              const float* __restrict__ w2, const float* __restrict__ b2,
                              float* __restrict__ out) {
    int b = blockIdx.x;
    int j = threadIdx.x;  // 128
    float s = b1[j];
    for (int k = 0; k < DREV; k++) s += pbatch[b * DREV + k] * w1[j * DREV + k];
    float a = seluf(s) * w2[j];
    __shared__ float red[128];
    red[j] = a;
    __syncthreads();
    for (int st = 64; st > 0; st >>= 1) {
        if (j < st) red[j] += red[j + st];
        __syncthreads();
    }
    if (j == 0) out[9 + b] = red[0] + b2[0];
}

// ---------------- p_stars head ----------------
__global__ void pstars_kernel(const float* __restrict__ doc,
                              const float* __restrict__ w1, const float* __restrict__ b1,
                              const float* __restrict__ w2, const float* __restrict__ b2,
                              float* __restrict__ out) {
    int j = threadIdx.x;  // 128
    __shared__ float hid[128];
    float s = b1[j];
    for (int k = 0; k < HD; k++) s += (doc[k] + doc[HD + k]) * w1[j * HD + k];
    hid[j] = seluf(s);
    __syncthreads();
    if (j < 9) {
        float o = b2[j];
        for (int k = 0; k < 128; k++) o += hid[k] * w2[j * 128 + k];
        out[j] = o;
    }
}

// ---------------- launch ----------------
extern "C" void kernel_launch(void* const* d_in, const int* in_sizes, int n_in,
                              void* d_out, int out_size) {
    (void)in_sizes; (void)n_in; (void)out_size;
    const int*   inputs     = (const int*)d_in[0];
    // d_in[1]=sent_lengths, d_in[2]=sent_counts : unused by reference
    const float* user_feats = (const float*)d_in[3];
    const float* embed      = (const float*)d_in[4];
    const float* wg_wih = (const float*)d_in[5];
    const float* wg_whh = (const float*)d_in[6];
    const float* wg_bih = (const float*)d_in[7];
    const float* wg_bhh = (const float*)d_in[8];
    const float* sg_wih = (const float*)d_in[9];
    const float* sg_whh = (const float*)d_in[10];
    const float* sg_bih = (const float*)d_in[11];
    const float* sg_bhh = (const float*)d_in[12];
    const float* rg_wih = (const float*)d_in[13];
    const float* rg_whh = (const float*)d_in[14];
    const float* rg_bih = (const float*)d_in[15];
    const float* rg_bhh = (const float*)d_in[16];
    const float* rfc_w1 = (const float*)d_in[17];
    const float* rfc_b1 = (const float*)d_in[18];
    const float* rfc_w2 = (const float*)d_in[19];
    const float* rfc_b2 = (const float*)d_in[20];
    const float* pfc_w1 = (const float*)d_in[21];
    const float* pfc_b1 = (const float*)d_in[22];
    const float* pfc_w2 = (const float*)d_in[23];
    const float* pfc_b2 = (const float*)d_in[24];
    const float* uf_w   = (const float*)d_in[25];
    float* out = (float*)d_out;

    float *wgTih, *wgThh, *sgTih, *sgThh, *rgTih, *rgThh;
    float *gxw, *gxs, *gxr, *sent, *rev, *pbatch, *doc;
    cudaGetSymbolAddress((void**)&wgTih, g_wgT_ih);
    cudaGetSymbolAddress((void**)&wgThh, g_wgT_hh);
    cudaGetSymbolAddress((void**)&sgTih, g_sgT_ih);
    cudaGetSymbolAddress((void**)&sgThh, g_sgT_hh);
    cudaGetSymbolAddress((void**)&rgTih, g_rgT_ih);
    cudaGetSymbolAddress((void**)&rgThh, g_rgT_hh);
    cudaGetSymbolAddress((void**)&gxw,   g_gx_w);
    cudaGetSymbolAddress((void**)&gxs,   g_gx_s);
    cudaGetSymbolAddress((void**)&gxr,   g_gx_r);
    cudaGetSymbolAddress((void**)&sent,  g_sent);
    cudaGetSymbolAddress((void**)&rev,   g_rev);
    cudaGetSymbolAddress((void**)&pbatch,g_pbatch);
    cudaGetSymbolAddress((void**)&doc,   g_doc);

    // 1. transpose all GRU weights to [dir][Kpad][768]
    {
        int tot, nb;
        cudaMemsetAsync(rgTih, 0, sizeof(float) * 2 * DREVP * GG);
        tot = 2 * GG * 256; nb = (tot + 255) / 256;
        transpose_kernel<<<nb, 256>>>(wg_wih, wgTih, 256, 256);
        transpose_kernel<<<nb, 256>>>(wg_whh, wgThh, 256, 256);
        transpose_kernel<<<nb, 256>>>(sg_wih, sgTih, 256, 256);
        transpose_kernel<<<nb, 256>>>(sg_whh, sgThh, 256, 256);
        transpose_kernel<<<nb, 256>>>(rg_whh, rgThh, 256, 256);
        tot = 2 * GG * DREV; nb = (tot + 255) / 256;
        transpose_kernel<<<nb, 256>>>(rg_wih, rgTih, DREV, DREVP);
    }

    // 2. word level: input-gate GEMM over all 131072 tokens, then recurrent pass
    gates_gemm_kernel<0, 256, 256, 16><<<dim3(NTOK_W / 16, 2), 256>>>(
        inputs, embed, nullptr, nullptr, wgTih, wg_bih, gxw, NTOK_W);
    gru_rec_kernel<16, NWORD><<<dim3(NSENT / 16, 2), 256>>>(
        gxw, wgThh, wg_bhh, sent, NSENT);

    // 3. sentence level
    gates_gemm_kernel<1, 256, 256, 16><<<dim3(NSENT / 16, 2), 256>>>(
        nullptr, nullptr, sent, sent + NSENT * HD, sgTih, sg_bih, gxs, NSENT);
    gru_rec_kernel<2, SPR><<<dim3(NREV / 2, 2), 256>>>(
        gxs, sgThh, sg_bhh, rev, NREV);

    // 4. p_batch = [rev_f+rev_b, normalize(user_feats)*uf_w]
    pbatch_kernel<<<NREV, 288>>>(rev, rev + NREV * HD, user_feats, uf_w, pbatch);

    // 5. r_stars head -> out[9..73)
    rstars_kernel<<<NREV, 128>>>(pbatch, rfc_w1, rfc_b1, rfc_w2, rfc_b2, out);

    // 6. review level: input-gate GEMM (K padded to 288) then batch-1 recurrent pass
    gates_gemm_kernel<2, DREVP, DREV, 16><<<dim3(NREV / 16, 2), 256>>>(
        nullptr, nullptr, pbatch, nullptr, rgTih, rg_bih, gxr, NREV);
    gru_rec1_kernel<<<2, 256>>>(gxr, rgThh, rg_bhh, doc);

    // 7. p_stars head -> out[0..9)
    pstars_kernel<<<1, 128>>>(doc, pfc_w1, pfc_b1, pfc_w2, pfc_b2, out);
}

// round 5
// speedup vs baseline: 2.6580x; 1.1896x over previous
#include <cuda_runtime.h>
#include <math.h>

// Problem constants
#define HD 256          // hidden dim
#define GG 768          // 3*H gates
#define NV 50000        // vocabulary size
#define NSENT 2048      // R*S sentences
#define NWORD 64        // words per sentence
#define NREV 64         // reviews
#define SPR 32          // sentences per review
#define DREV 276        // H + UF
#define DREVP 288       // padded to multiple of 16
#define UF 20

typedef unsigned long long u64;

// ---------------- scratch (static device arrays; no allocation allowed) ----------------
__device__ float g_wgT_ih[2 * 256 * GG];
__device__ float g_wgT_hh[2 * 256 * GG];
__device__ float g_sgT_ih[2 * 256 * GG];
__device__ float g_sgT_hh[2 * 256 * GG];
__device__ float g_rgT_ih[2 * DREVP * GG];
__device__ float g_rgT_hh[2 * 256 * GG];
__device__ float g_gx_v[(size_t)2 * NV * GG];      // per-VOCAB input-gates (307 MB)
__device__ float g_gx_s[2 * NSENT * GG];           // sentence input-gates
__device__ float g_gx_r[2 * NREV * GG];            // review input-gates
__device__ float g_sent[2 * NSENT * HD];
__device__ float g_rev[2 * NREV * HD];
__device__ float g_pbatch[NREV * DREV];
__device__ float g_doc[2 * HD];

// ---------------- helpers ----------------
__device__ __forceinline__ float sigf(float x) { return 1.0f / (1.0f + __expf(-x)); }

__device__ __forceinline__ float seluf(float x) {
    const float alpha = 1.6732632423543772f;
    const float scale = 1.0507009873554805f;
    return x > 0.0f ? scale * x : scale * alpha * (expf(x) - 1.0f);
}

__device__ __forceinline__ u64 pack2(float lo, float hi) {
    u64 r; asm("mov.b64 %0, {%1, %2};" : "=l"(r) : "f"(lo), "f"(hi)); return r;
}
__device__ __forceinline__ void unpack2(u64 v, float& lo, float& hi) {
    asm("mov.b64 {%0, %1}, %2;" : "=f"(lo), "=f"(hi) : "l"(v));
}
// packed dual fp32 FMA
__device__ __forceinline__ u64 fma2(u64 a, u64 b, u64 c) {
    u64 d; asm("fma.rn.f32x2 %0, %1, %2, %3;" : "=l"(d) : "l"(a), "l"(b), "l"(c)); return d;
}
__device__ __forceinline__ void pf_l1(const float* p) {
    asm volatile("prefetch.global.L1 [%0];" :: "l"(p));
}

// prefetch U consecutive k-rows of the 3 gate columns owned by this thread
template <int U>
__device__ __forceinline__ void load_wchunk(float (&w)[3][U], const float* __restrict__ base, int kb) {
#pragma unroll
    for (int u = 0; u < U; u++) {
        const float* p = base + (size_t)(kb + u) * GG;
        w[0][u] = __ldg(p);
        w[1][u] = __ldg(p + 256);
        w[2][u] = __ldg(p + 512);
    }
}

template <int U, int P, int K>
__device__ __forceinline__ void fma_chunk(u64 (&acc)[P][3], const float (&w)[3][U],
                                          const float2 (*sx)[K], int kb) {
#pragma unroll
    for (int u = 0; u < U; u++) {
        const u64 w0p = pack2(w[0][u], w[0][u]);
        const u64 w1p = pack2(w[1][u], w[1][u]);
        const u64 w2p = pack2(w[2][u], w[2][u]);
#pragma unroll
        for (int p = 0; p < P; p++) {
            const u64 xp = *reinterpret_cast<const u64*>(&sx[p][kb + u]);
            acc[p][0] = fma2(xp, w0p, acc[p][0]);
            acc[p][1] = fma2(xp, w1p, acc[p][1]);
            acc[p][2] = fma2(xp, w2p, acc[p][2]);
        }
    }
}

// ---------------- weight transpose: src [2][768][Din] -> dst [2][Dpad][768] ----------------
__global__ void transpose_kernel(const float* __restrict__ src, float* __restrict__ dst,
                                 int Din, int Dpad) {
    int idx = blockIdx.x * blockDim.x + threadIdx.x;
    int total = 2 * GG * Din;
    if (idx >= total) return;
    int g = idx % GG;
    int rem = idx / GG;
    int k = rem % Din;
    int d = rem / Din;
    dst[((size_t)d * Dpad + k) * GG + g] = src[((size_t)d * GG + g) * Din + k];
}

// ---------------- input-gates GEMM: gx[dir][row][768] = x @ WihT + bih ----------------
// MODE 0: x = embed[row]          (vocabulary rows — word level)
// MODE 1: x = xin0[row]+xin1[row] (sentence level)
// MODE 2: x = xin0[row]  (review level, true K = KD, padded to K)
template <int MODE, int K, int KD, int TOKS>
__global__ __launch_bounds__(256, 2)
void gates_gemm_kernel(const float* __restrict__ embed,
                       const float* __restrict__ xin0,
                       const float* __restrict__ xin1,
                       const float* __restrict__ wT_ih,
                       const float* __restrict__ bih,
                       float* __restrict__ gx, int M) {
    constexpr int P = TOKS / 2;
    constexpr int U = 4;
    const int dir  = blockIdx.y;
    const int tok0 = blockIdx.x * TOKS;
    const int t0   = threadIdx.x;

    __shared__ float2 sx2[P][K];   // [pair][k], k contiguous

#pragma unroll
    for (int p = 0; p < P; p++) {
        const int ta = tok0 + 2 * p, tb = ta + 1;
        for (int k = t0; k < K; k += 256) {
            float xa, xb;
            if (MODE == 0) {
                xa = embed[(size_t)ta * HD + k];
                xb = embed[(size_t)tb * HD + k];
            } else if (MODE == 1) {
                xa = xin0[(size_t)ta * HD + k] + xin1[(size_t)ta * HD + k];
                xb = xin0[(size_t)tb * HD + k] + xin1[(size_t)tb * HD + k];
            } else {
                xa = (k < KD) ? xin0[(size_t)ta * KD + k] : 0.0f;
                xb = (k < KD) ? xin0[(size_t)tb * KD + k] : 0.0f;
            }
            sx2[p][k] = make_float2(xa, xb);
        }
    }
    __syncthreads();

    const float* wbase = wT_ih + (size_t)dir * K * GG + t0;
    u64 acc[P][3];
#pragma unroll
    for (int p = 0; p < P; p++) acc[p][0] = acc[p][1] = acc[p][2] = 0ull;

    float wA[3][U], wB[3][U];
    load_wchunk<U>(wA, wbase, 0);
#pragma unroll 1
    for (int kb = 0; kb < K; kb += 2 * U) {
        load_wchunk<U>(wB, wbase, kb + U);
        fma_chunk<U, P, K>(acc, wA, sx2, kb);
        if (kb + 2 * U < K) load_wchunk<U>(wA, wbase, kb + 2 * U);
        fma_chunk<U, P, K>(acc, wB, sx2, kb + U);
    }

    const float bi0 = bih[dir * GG + t0];
    const float bi1 = bih[dir * GG + 256 + t0];
    const float bi2 = bih[dir * GG + 512 + t0];
#pragma unroll
    for (int p = 0; p < P; p++) {
        float a0, b0, a1, b1, a2, b2;
        unpack2(acc[p][0], a0, b0);
        unpack2(acc[p][1], a1, b1);
        unpack2(acc[p][2], a2, b2);
        float* oa = gx + ((size_t)dir * M + tok0 + 2 * p) * GG;
        float* ob = oa + GG;
        oa[t0]       = a0 + bi0;  ob[t0]       = b0 + bi0;
        oa[256 + t0] = a1 + bi1;  ob[256 + t0] = b1 + bi1;
        oa[512 + t0] = a2 + bi2;  ob[512 + t0] = b2 + bi2;
    }
}

// ---------------- recurrent GRU, row-paired f32x2 ----------------
// IDX=1: gate rows gathered via widx (gx holds per-vocab gates, gxM = NV)
// IDX=0: gate rows direct at row*T+te (gxM = nbatch*T)
template <int IDX, int ROWS, int T>
__global__ __launch_bounds__(256, 2)
void gru_rec_kernel(const int* __restrict__ widx,
                    const float* __restrict__ gx, int gxM,
                    const float* __restrict__ wT_hh,
                    const float* __restrict__ bhh,
                    float* __restrict__ out, int nbatch) {
    constexpr int P = ROWS / 2;
    constexpr int U = 4;
    const int dir  = blockIdx.y;
    const int row0 = blockIdx.x * ROWS;
    const int t0   = threadIdx.x;

    __shared__ float2 sh2[P][HD];
#pragma unroll
    for (int p = 0; p < P; p++) sh2[p][t0] = make_float2(0.0f, 0.0f);

    const float* wbase = wT_hh + (size_t)dir * HD * GG + t0;
    const float bh0 = bhh[dir * GG + t0];
    const float bh1 = bhh[dir * GG + 256 + t0];
    const float bh2 = bhh[dir * GG + 512 + t0];
    __syncthreads();

    for (int t = 0; t < T; t++) {
        const int te = dir ? (T - 1 - t) : t;

        // prefetch this step's gate rows into L1 (no registers held)
#pragma unroll
        for (int p = 0; p < P; p++) {
            const int ra = row0 + 2 * p, rb = ra + 1;
            const long ia = IDX ? (long)widx[ra * T + te] : (long)ra * T + te;
            const long ib = IDX ? (long)widx[rb * T + te] : (long)rb * T + te;
            const float* ga = gx + ((size_t)dir * gxM + ia) * GG + t0;
            const float* gb = gx + ((size_t)dir * gxM + ib) * GG + t0;
            pf_l1(ga); pf_l1(ga + 256); pf_l1(ga + 512);
            pf_l1(gb); pf_l1(gb + 256); pf_l1(gb + 512);
        }

        u64 ah[P][3];
#pragma unroll
        for (int p = 0; p < P; p++) ah[p][0] = ah[p][1] = ah[p][2] = 0ull;

        float wA[3][U], wB[3][U];
        load_wchunk<U>(wA, wbase, 0);
#pragma unroll 1
        for (int kb = 0; kb < HD; kb += 2 * U) {
            load_wchunk<U>(wB, wbase, kb + U);
            fma_chunk<U, P, HD>(ah, wA, sh2, kb);
            if (kb + 2 * U < HD) load_wchunk<U>(wA, wbase, kb + 2 * U);
            fma_chunk<U, P, HD>(ah, wB, sh2, kb + U);
        }
        __syncthreads();  // all reads of sh2 done before writes

#pragma unroll
        for (int p = 0; p < P; p++) {
            const int ra = row0 + 2 * p, rb = ra + 1;
            const long ia = IDX ? (long)widx[ra * T + te] : (long)ra * T + te;
            const long ib = IDX ? (long)widx[rb * T + te] : (long)rb * T + te;
            const float* ga = gx + ((size_t)dir * gxM + ia) * GG;
            const float* gb = gx + ((size_t)dir * gxM + ib) * GG;
            const float x0a = ga[t0], x1a = ga[256 + t0], x2a = ga[512 + t0];
            const float x0b = gb[t0], x1b = gb[256 + t0], x2b = gb[512 + t0];
            float h0a, h0b, h1a, h1b, h2a, h2b;
            unpack2(ah[p][0], h0a, h0b); unpack2(ah[p][1], h1a, h1b); unpack2(ah[p][2], h2a, h2b);
            const float2 hold = sh2[p][t0];
            const float rga = sigf(x0a + h0a + bh0), rgb = sigf(x0b + h0b + bh0);
            const float za  = sigf(x1a + h1a + bh1), zb  = sigf(x1b + h1b + bh1);
            const float na  = tanhf(x2a + rga * (h2a + bh2));
            const float nb  = tanhf(x2b + rgb * (h2b + bh2));
            sh2[p][t0] = make_float2((1.0f - za) * na + za * hold.x,
                                     (1.0f - zb) * nb + zb * hold.y);
        }
        __syncthreads();
    }

#pragma unroll
    for (int p = 0; p < P; p++) {
        const float2 h = sh2[p][t0];
        out[((size_t)dir * nbatch + row0 + 2 * p) * HD + t0]     = h.x;
        out[((size_t)dir * nbatch + row0 + 2 * p + 1) * HD + t0] = h.y;
    }
}

// ---------------- review-level recurrent GRU (batch 1, scalar) ----------------
__global__ void gru_rec1_kernel(const float* __restrict__ gx,
                                const float* __restrict__ wT_hh,
                                const float* __restrict__ bhh,
                                float* __restrict__ out) {
    const int dir = blockIdx.x;
    const int t0  = threadIdx.x;
    __shared__ float sh[HD];
    sh[t0] = 0.0f;
    const float* whh = wT_hh + (size_t)dir * HD * GG;
    const float bh0 = bhh[dir * GG + t0];
    const float bh1 = bhh[dir * GG + 256 + t0];
    const float bh2 = bhh[dir * GG + 512 + t0];
    __syncthreads();

    for (int t = 0; t < NREV; t++) {
        const int te = dir ? (NREV - 1 - t) : t;
        const float* ga = gx + ((size_t)dir * NREV + te) * GG;
        const float x0 = ga[t0], x1 = ga[256 + t0], x2 = ga[512 + t0];
        float a0 = 0.0f, a1 = 0.0f, a2 = 0.0f;
#pragma unroll 8
        for (int k = 0; k < HD; k++) {
            const float hk = sh[k];
            a0 += hk * whh[(size_t)k * GG + t0];
            a1 += hk * whh[(size_t)k * GG + 256 + t0];
            a2 += hk * whh[(size_t)k * GG + 512 + t0];
        }
        const float hold = sh[t0];
        __syncthreads();
        const float r = sigf(x0 + a0 + bh0);
        const float z = sigf(x1 + a1 + bh1);
        const float n = tanhf(x2 + r * (a2 + bh2));
        sh[t0] = (1.0f - z) * n + z * hold;
        __syncthreads();
    }
    out[dir * HD + t0] = sh[t0];
}

// ---------------- p_batch = [rev_f + rev_b, normalize(uf)*uf_w] ----------------
__global__ void pbatch_kernel(const float* __restrict__ rev0,
                              const float* __restrict__ rev1,
                              const float* __restrict__ user_feats,
                              const float* __restrict__ uf_w,
                              float* __restrict__ pbatch) {
    int b = blockIdx.x;
    int t = threadIdx.x;  // 288 threads
    if (t < HD) {
        pbatch[b * DREV + t] = rev0[b * HD + t] + rev1[b * HD + t];
    } else {
        int lane = t - HD;
        float v = (lane < UF) ? user_feats[b * UF + lane] : 0.0f;
        float s = v * v;
#pragma unroll
        for (int o = 16; o > 0; o >>= 1) s += __shfl_xor_sync(0xffffffffu, s, o);
        float nrm = fmaxf(sqrtf(s), 1e-12f);
        if (lane < UF) pbatch[b * DREV + HD + lane] = (v / nrm) * uf_w[lane];
    }
}

// ---------------- r_stars head ----------------
__global__ void rstars_kernel(const float* __restrict__ pbatch,
                              const float* __restrict__ w1, const float* __restrict__ b1,
                              const float* __restrict__ w2, const float* __restrict__ b2,
                              float* __restrict__ out) {
    int b = blockIdx.x;
    int j = threadIdx.x;  // 128
    float s = b1[j];
    for (int k = 0; k < DREV; k++) s += pbatch[b * DREV + k] * w1[j * DREV + k];
    float a = seluf(s) * w2[j];
    __shared__ float red[128];
    red[j] = a;
    __syncthreads();
    for (int st = 64; st > 0; st >>= 1) {
        if (j < st) red[j] += red[j + st];
        __syncthreads();
    }
    if (j == 0) out[9 + b] = red[0] + b2[0];
}

// ---------------- p_stars head ----------------
__global__ void pstars_kernel(const float* __restrict__ doc,
                              const float* __restrict__ w1, const float* __restrict__ b1,
                              const float* __restrict__ w2, const float* __restrict__ b2,
                              float* __restrict__ out) {
    int j = threadIdx.x;  // 128
    __shared__ float hid[128];
    float s = b1[j];
    for (int k = 0; k < HD; k++) s += (doc[k] + doc[HD + k]) * w1[j * HD + k];
    hid[j] = seluf(s);
    __syncthreads();
    if (j < 9) {
        float o = b2[j];
        for (int k = 0; k < 128; k++) o += hid[k] * w2[j * 128 + k];
        out[j] = o;
    }
}

// ---------------- launch ----------------
extern "C" void kernel_launch(void* const* d_in, const int* in_sizes, int n_in,
                              void* d_out, int out_size) {
    (void)in_sizes; (void)n_in; (void)out_size;
    const int*   inputs     = (const int*)d_in[0];
    // d_in[1]=sent_lengths, d_in[2]=sent_counts : unused by reference
    const float* user_feats = (const float*)d_in[3];
    const float* embed      = (const float*)d_in[4];
    const float* wg_wih = (const float*)d_in[5];
    const float* wg_whh = (const float*)d_in[6];
    const float* wg_bih = (const float*)d_in[7];
    const float* wg_bhh = (const float*)d_in[8];
    const float* sg_wih = (const float*)d_in[9];
    const float* sg_whh = (const float*)d_in[10];
    const float* sg_bih = (const float*)d_in[11];
    const float* sg_bhh = (const float*)d_in[12];
    const float* rg_wih = (const float*)d_in[13];
    const float* rg_whh = (const float*)d_in[14];
    const float* rg_bih = (const float*)d_in[15];
    const float* rg_bhh = (const float*)d_in[16];
    const float* rfc_w1 = (const float*)d_in[17];
    const float* rfc_b1 = (const float*)d_in[18];
    const float* rfc_w2 = (const float*)d_in[19];
    const float* rfc_b2 = (const float*)d_in[20];
    const float* pfc_w1 = (const float*)d_in[21];
    const float* pfc_b1 = (const float*)d_in[22];
    const float* pfc_w2 = (const float*)d_in[23];
    const float* pfc_b2 = (const float*)d_in[24];
    const float* uf_w   = (const float*)d_in[25];
    float* out = (float*)d_out;

    float *wgTih, *wgThh, *sgTih, *sgThh, *rgTih, *rgThh;
    float *gxv, *gxs, *gxr, *sent, *rev, *pbatch, *doc;
    cudaGetSymbolAddress((void**)&wgTih, g_wgT_ih);
    cudaGetSymbolAddress((void**)&wgThh, g_wgT_hh);
    cudaGetSymbolAddress((void**)&sgTih, g_sgT_ih);
    cudaGetSymbolAddress((void**)&sgThh, g_sgT_hh);
    cudaGetSymbolAddress((void**)&rgTih, g_rgT_ih);
    cudaGetSymbolAddress((void**)&rgThh, g_rgT_hh);
    cudaGetSymbolAddress((void**)&gxv,   g_gx_v);
    cudaGetSymbolAddress((void**)&gxs,   g_gx_s);
    cudaGetSymbolAddress((void**)&gxr,   g_gx_r);
    cudaGetSymbolAddress((void**)&sent,  g_sent);
    cudaGetSymbolAddress((void**)&rev,   g_rev);
    cudaGetSymbolAddress((void**)&pbatch,g_pbatch);
    cudaGetSymbolAddress((void**)&doc,   g_doc);

    // 1. transpose all GRU weights to [dir][Kpad][768]
    {
        int tot, nb;
        cudaMemsetAsync(rgTih, 0, sizeof(float) * 2 * DREVP * GG);
        tot = 2 * GG * 256; nb = (tot + 255) / 256;
        transpose_kernel<<<nb, 256>>>(wg_wih, wgTih, 256, 256);
        transpose_kernel<<<nb, 256>>>(wg_whh, wgThh, 256, 256);
        transpose_kernel<<<nb, 256>>>(sg_wih, sgTih, 256, 256);
        transpose_kernel<<<nb, 256>>>(sg_whh, sgThh, 256, 256);
        transpose_kernel<<<nb, 256>>>(rg_whh, rgThh, 256, 256);
        tot = 2 * GG * DREV; nb = (tot + 255) / 256;
        transpose_kernel<<<nb, 256>>>(rg_wih, rgTih, DREV, DREVP);
    }

    // 2. word level: input gates per VOCABULARY row (50000 rows), then recurrent
    //    pass gathers gate rows via the token indices.
    gates_gemm_kernel<0, 256, 256, 16><<<dim3(NV / 16, 2), 256>>>(
        embed, nullptr, nullptr, wgTih, wg_bih, gxv, NV);
    gru_rec_kernel<1, 16, NWORD><<<dim3(NSENT / 16, 2), 256>>>(
        inputs, gxv, NV, wgThh, wg_bhh, sent, NSENT);

    // 3. sentence level
    gates_gemm_kernel<1, 256, 256, 16><<<dim3(NSENT / 16, 2), 256>>>(
        nullptr, sent, sent + NSENT * HD, sgTih, sg_bih, gxs, NSENT);
    gru_rec_kernel<0, 2, SPR><<<dim3(NREV / 2, 2), 256>>>(
        nullptr, gxs, NSENT, sgThh, sg_bhh, rev, NREV);

    // 4. p_batch = [rev_f+rev_b, normalize(user_feats)*uf_w]
    pbatch_kernel<<<NREV, 288>>>(rev, rev + NREV * HD, user_feats, uf_w, pbatch);

    // 5. r_stars head -> out[9..73)
    rstars_kernel<<<NREV, 128>>>(pbatch, rfc_w1, rfc_b1, rfc_w2, rfc_b2, out);

    // 6. review level: input-gate GEMM (K padded to 288) then batch-1 recurrent
    gates_gemm_kernel<2, DREVP, DREV, 16><<<dim3(NREV / 16, 2), 256>>>(
        nullptr, pbatch, nullptr, rgTih, rg_bih, gxr, NREV);
    gru_rec1_kernel<<<2, 256>>>(gxr, rgThh, rg_bhh, doc);

    // 7. p_stars head -> out[0..9)
    pstars_kernel<<<1, 128>>>(doc, pfc_w1, pfc_b1, pfc_w2, pfc_b2, out);
}

// round 8
// speedup vs baseline: 2.7798x; 1.0458x over previous
#include <cuda_runtime.h>
#include <cuda_bf16.h>
#include <math.h>

// Problem constants
#define HD 256          // hidden dim
#define GG 768          // 3*H gates
#define NV 50000        // vocabulary size
#define NVT ((NV + 127) / 128)   // vocab tiles (391)
#define NSENT 2048      // R*S sentences
#define NWORD 64        // words per sentence
#define NREV 64         // reviews
#define SPR 32          // sentences per review
#define DREV 276        // H + UF
#define DREVP 288       // padded
#define UF 20

typedef unsigned long long u64;
typedef unsigned int u32;
typedef unsigned short u16;

// ---------------- scratch (static device arrays; no allocation allowed) ----------------
__device__ float g_wgT_hh[2 * 256 * GG];
__device__ float g_sgT_ih[2 * 256 * GG];
__device__ float g_sgT_hh[2 * 256 * GG];
__device__ float g_rgT_ih[2 * DREVP * GG];
__device__ float g_rgT_hh[2 * 256 * GG];
__device__ __nv_bfloat16 g_wih_hi[2 * GG * 256];   // split-bf16 word Wih (native [g][k])
__device__ __nv_bfloat16 g_wih_lo[2 * GG * 256];
__device__ float g_gx_v[(size_t)2 * NV * GG];      // per-VOCAB input-gates (307 MB)
__device__ float g_gx_s[2 * NSENT * GG];
__device__ float g_gx_r[2 * NREV * GG];
__device__ float g_sent[2 * NSENT * HD];
__device__ float g_rev[2 * NREV * HD];
__device__ float g_pbatch[NREV * DREV];
__device__ float g_doc[2 * HD];

// ---------------- helpers ----------------
__device__ __forceinline__ float sigf(float x) { return 1.0f / (1.0f + __expf(-x)); }

__device__ __forceinline__ float seluf(float x) {
    const float alpha = 1.6732632423543772f;
    const float scale = 1.0507009873554805f;
    return x > 0.0f ? scale * x : scale * alpha * (expf(x) - 1.0f);
}

__device__ __forceinline__ u64 pack2(float lo, float hi) {
    u64 r; asm("mov.b64 %0, {%1, %2};" : "=l"(r) : "f"(lo), "f"(hi)); return r;
}
__device__ __forceinline__ void unpack2(u64 v, float& lo, float& hi) {
    asm("mov.b64 {%0, %1}, %2;" : "=f"(lo), "=f"(hi) : "l"(v));
}
__device__ __forceinline__ u64 fma2(u64 a, u64 b, u64 c) {
    u64 d; asm("fma.rn.f32x2 %0, %1, %2, %3;" : "=l"(d) : "l"(a), "l"(b), "l"(c)); return d;
}
__device__ __forceinline__ void pf_l1(const float* p) {
    asm volatile("prefetch.global.L1 [%0];" :: "l"(p));
}
__device__ __forceinline__ u32 smem_u32(const void* p) {
    u32 a; asm("{ .reg .u64 t; cvta.to.shared.u64 t, %1; cvt.u32.u64 %0, t; }" : "=r"(a) : "l"(p));
    return a;
}

// ---------------- baseline-PTX tensor core wrappers (sm_80+; OK for compute_103) ----------
__device__ __forceinline__ void ldm_x4(u32& r0, u32& r1, u32& r2, u32& r3, u32 addr) {
    asm volatile("ldmatrix.sync.aligned.m8n8.x4.shared.b16 {%0,%1,%2,%3}, [%4];"
                 : "=r"(r0), "=r"(r1), "=r"(r2), "=r"(r3) : "r"(addr));
}
__device__ __forceinline__ void mma_bf16(float* d, const u32* a, u32 b0, u32 b1) {
    asm volatile("mma.sync.aligned.m16n8k16.row.col.f32.bf16.bf16.f32 "
                 "{%0,%1,%2,%3}, {%4,%5,%6,%7}, {%8,%9}, {%0,%1,%2,%3};"
                 : "+f"(d[0]), "+f"(d[1]), "+f"(d[2]), "+f"(d[3])
                 : "r"(a[0]), "r"(a[1]), "r"(a[2]), "r"(a[3]), "r"(b0), "r"(b1));
}

// split fp32 -> (hi, lo) bf16
__device__ __forceinline__ void bf_split(float x, u16& hb, u16& lb) {
    __nv_bfloat16 h = __float2bfloat16_rn(x);
    float r = x - __bfloat162float(h);
    __nv_bfloat16 l = __float2bfloat16_rn(r);
    hb = __bfloat16_as_ushort(h);
    lb = __bfloat16_as_ushort(l);
}

// ---------------- prep: split Wih into bf16 hi/lo (native [2][768][256] layout) ----------
__global__ void wsplit_kernel(const float* __restrict__ src,
                              __nv_bfloat16* __restrict__ dhi,
                              __nv_bfloat16* __restrict__ dlo, int n) {
    int i = blockIdx.x * blockDim.x + threadIdx.x;
    if (i >= n) return;
    u16 hb, lb;
    bf_split(src[i], hb, lb);
    dhi[i] = __ushort_as_bfloat16(hb);
    dlo[i] = __ushort_as_bfloat16(lb);
}

// ---------------- weight transpose: src [2][768][Din] -> dst [2][Dpad][768] ----------------
__global__ void transpose_kernel(const float* __restrict__ src, float* __restrict__ dst,
                                 int Din, int Dpad) {
    int idx = blockIdx.x * blockDim.x + threadIdx.x;
    int total = 2 * GG * Din;
    if (idx >= total) return;
    int g = idx % GG;
    int rem = idx / GG;
    int k = rem % Din;
    int d = rem / Din;
    dst[((size_t)d * Dpad + k) * GG + g] = src[((size_t)d * GG + g) * Din + k];
}

// ================= HMMA (mma.sync) vocab input-gate GEMM =================
// gxv[dir][v][g] = sum_k embed[v][k] * Wih[dir][g][k] + bih[dir][g]
// split-bf16 3-term: Ehi*Whi + Ehi*Wlo + Elo*Whi, fp32 accumulate.
// CTA: 128 vocab rows; 12 chunks of 64 gates; 8 warps = 8 x (16 rows x 64 gates).
#define ASTRIDE 264                    // bf16 elems per padded row (33 x 16B, odd -> no conflicts)
#define OFF_AHI 0
#define OFF_ALO (128 * ASTRIDE)
#define OFF_BHI (2 * 128 * ASTRIDE)
#define OFF_BLO (2 * 128 * ASTRIDE + 64 * ASTRIDE)
#define SMTOT   ((2 * 128 * ASTRIDE + 2 * 64 * ASTRIDE) * 2)   // bytes = 202752

__global__ __launch_bounds__(256)
void vocab_gemm_mma(const float* __restrict__ embed,
                    const __nv_bfloat16* __restrict__ whi,
                    const __nv_bfloat16* __restrict__ wlo,
                    const float* __restrict__ bih,
                    float* __restrict__ gxv) {
    extern __shared__ __nv_bfloat16 sm[];
    __nv_bfloat16* Ahi = sm + OFF_AHI;
    __nv_bfloat16* Alo = sm + OFF_ALO;
    __nv_bfloat16* Bhi = sm + OFF_BHI;
    __nv_bfloat16* Blo = sm + OFF_BLO;

    const int dir  = blockIdx.y;
    const int row0 = blockIdx.x * 128;
    const int tid  = threadIdx.x;
    const int lane = tid & 31;
    const int warp = tid >> 5;

    // ---- stage A (embed rows, split hi/lo) ----
    for (int i = tid; i < 128 * 64; i += 256) {     // 64 float4 per row
        int r = i >> 6, q = i & 63;
        int vr = row0 + r; if (vr >= NV) vr = NV - 1;
        float4 v = __ldg(reinterpret_cast<const float4*>(embed + (size_t)vr * HD) + q);
        u16 h0, l0, h1, l1, h2, l2, h3, l3;
        bf_split(v.x, h0, l0); bf_split(v.y, h1, l1);
        bf_split(v.z, h2, l2); bf_split(v.w, h3, l3);
        uint2 ph = make_uint2((u32)h0 | ((u32)h1 << 16), (u32)h2 | ((u32)h3 << 16));
        uint2 pl = make_uint2((u32)l0 | ((u32)l1 << 16), (u32)l2 | ((u32)l3 << 16));
        *reinterpret_cast<uint2*>(Ahi + r * ASTRIDE + q * 4) = ph;
        *reinterpret_cast<uint2*>(Alo + r * ASTRIDE + q * 4) = pl;
    }
    __syncthreads();

    // ldmatrix source addresses (bytes)
    // A: row = warp*16 + (lane&15), k-offset8 = (lane>>4)*8
    const u32 aRow = warp * 16 + (lane & 15);
    const u32 aK8  = (u32)(lane >> 4) << 3;
    const u32 aHiAddr = smem_u32(Ahi + aRow * ASTRIDE + aK8);
    const u32 aLoAddr = smem_u32(Alo + aRow * ASTRIDE + aK8);
    // B: n-row = pair*16 + (lane>>4)*8 + (lane&7), k-offset8 = ((lane>>3)&1)*8
    const u32 bRow = ((u32)(lane >> 4) << 3) + (lane & 7);
    const u32 bK8  = ((u32)(lane >> 3) & 1) << 3;
    const u32 bHiAddr = smem_u32(Bhi + bRow * ASTRIDE + bK8);
    const u32 bLoAddr = smem_u32(Blo + bRow * ASTRIDE + bK8);

    const int r0 = row0 + warp * 16 + (lane >> 2);

#pragma unroll 1
    for (int ch = 0; ch < 12; ch++) {
        // ---- stage B chunk: 64 gates x 256 k (hi + lo) ----
        {
            const __nv_bfloat16* srch = whi + ((size_t)dir * GG + ch * 64) * 256;
            const __nv_bfloat16* srcl = wlo + ((size_t)dir * GG + ch * 64) * 256;
            for (int i = tid; i < 64 * 32; i += 256) {      // 32 uint4 per gate row
                int r = i >> 5, q = i & 31;
                *reinterpret_cast<uint4*>(Bhi + r * ASTRIDE + q * 8) =
                    reinterpret_cast<const uint4*>(srch + (size_t)r * 256)[q];
                *reinterpret_cast<uint4*>(Blo + r * ASTRIDE + q * 8) =
                    reinterpret_cast<const uint4*>(srcl + (size_t)r * 256)[q];
            }
        }
        __syncthreads();

        float acc[8][4];
#pragma unroll
        for (int n = 0; n < 8; n++) { acc[n][0] = acc[n][1] = acc[n][2] = acc[n][3] = 0.0f; }

#pragma unroll 1
        for (int ks = 0; ks < 16; ks++) {
            u32 ah[4], al[4];
            ldm_x4(ah[0], ah[1], ah[2], ah[3], aHiAddr + ks * 32);
            ldm_x4(al[0], al[1], al[2], al[3], aLoAddr + ks * 32);
#pragma unroll
            for (int p = 0; p < 4; p++) {      // pairs of n-tiles
                u32 bh[4], bl[4];
                const u32 boff = (u32)(p * 16) * (ASTRIDE * 2) + ks * 32;
                ldm_x4(bh[0], bh[1], bh[2], bh[3], bHiAddr + boff);
                ldm_x4(bl[0], bl[1], bl[2], bl[3], bLoAddr + boff);
                mma_bf16(acc[2 * p],     ah, bh[0], bh[1]);
                mma_bf16(acc[2 * p],     ah, bl[0], bl[1]);
                mma_bf16(acc[2 * p],     al, bh[0], bh[1]);
                mma_bf16(acc[2 * p + 1], ah, bh[2], bh[3]);
                mma_bf16(acc[2 * p + 1], ah, bl[2], bl[3]);
                mma_bf16(acc[2 * p + 1], al, bh[2], bh[3]);
            }
        }
        __syncthreads();   // B smem reused next chunk

        // ---- epilogue: write 8 n-tiles with bias ----
        const int gbase = ch * 64 + 2 * (lane & 3);
#pragma unroll
        for (int nt = 0; nt < 8; nt++) {
            const int g = gbase + nt * 8;
            const float b0 = __ldg(bih + dir * GG + g);
            const float b1 = __ldg(bih + dir * GG + g + 1);
            if (r0 < NV) {
                float2 o = make_float2(acc[nt][0] + b0, acc[nt][1] + b1);
                *reinterpret_cast<float2*>(gxv + ((size_t)dir * NV + r0) * GG + g) = o;
            }
            if (r0 + 8 < NV) {
                float2 o = make_float2(acc[nt][2] + b0, acc[nt][3] + b1);
                *reinterpret_cast<float2*>(gxv + ((size_t)dir * NV + r0 + 8) * GG + g) = o;
            }
        }
    }
}

// ---------------- FFMA2 input-gates GEMM (sentence / review levels) ----------------
template <int U>
__device__ __forceinline__ void load_wchunk(float (&w)[3][U], const float* __restrict__ base, int kb) {
#pragma unroll
    for (int u = 0; u < U; u++) {
        const float* p = base + (size_t)(kb + u) * GG;
        w[0][u] = __ldg(p);
        w[1][u] = __ldg(p + 256);
        w[2][u] = __ldg(p + 512);
    }
}

template <int U, int P, int K>
__device__ __forceinline__ void fma_chunk(u64 (&acc)[P][3], const float (&w)[3][U],
                                          const float2 (*sx)[K], int kb) {
#pragma unroll
    for (int u = 0; u < U; u++) {
        const u64 w0p = pack2(w[0][u], w[0][u]);
        const u64 w1p = pack2(w[1][u], w[1][u]);
        const u64 w2p = pack2(w[2][u], w[2][u]);
#pragma unroll
        for (int p = 0; p < P; p++) {
            const u64 xp = *reinterpret_cast<const u64*>(&sx[p][kb + u]);
            acc[p][0] = fma2(xp, w0p, acc[p][0]);
            acc[p][1] = fma2(xp, w1p, acc[p][1]);
            acc[p][2] = fma2(xp, w2p, acc[p][2]);
        }
    }
}

// MODE 1: x = xin0[row]+xin1[row] (sentence level)
// MODE 2: x = xin0[row]  (review level, true K = KD, padded to K)
template <int MODE, int K, int KD, int TOKS>
__global__ __launch_bounds__(256, 2)
void gates_gemm_kernel(const float* __restrict__ xin0,
                       const float* __restrict__ xin1,
                       const float* __restrict__ wT_ih,
                       const float* __restrict__ bih,
                       float* __restrict__ gx, int M) {
    constexpr int P = TOKS / 2;
    constexpr int U = 4;
    const int dir  = blockIdx.y;
    const int tok0 = blockIdx.x * TOKS;
    const int t0   = threadIdx.x;

    __shared__ float2 sx2[P][K];

#pragma unroll
    for (int p = 0; p < P; p++) {
        const int ta = tok0 + 2 * p, tb = ta + 1;
        for (int k = t0; k < K; k += 256) {
            float xa, xb;
            if (MODE == 1) {
                xa = xin0[(size_t)ta * HD + k] + xin1[(size_t)ta * HD + k];
                xb = xin0[(size_t)tb * HD + k] + xin1[(size_t)tb * HD + k];
            } else {
                xa = (k < KD) ? xin0[(size_t)ta * KD + k] : 0.0f;
                xb = (k < KD) ? xin0[(size_t)tb * KD + k] : 0.0f;
            }
            sx2[p][k] = make_float2(xa, xb);
        }
    }
    __syncthreads();

    const float* wbase = wT_ih + (size_t)dir * K * GG + t0;
    u64 acc[P][3];
#pragma unroll
    for (int p = 0; p < P; p++) acc[p][0] = acc[p][1] = acc[p][2] = 0ull;

    float wA[3][U], wB[3][U];
    load_wchunk<U>(wA, wbase, 0);
#pragma unroll 1
    for (int kb = 0; kb < K; kb += 2 * U) {
        load_wchunk<U>(wB, wbase, kb + U);
        fma_chunk<U, P, K>(acc, wA, sx2, kb);
        if (kb + 2 * U < K) load_wchunk<U>(wA, wbase, kb + 2 * U);
        fma_chunk<U, P, K>(acc, wB, sx2, kb + U);
    }

    const float bi0 = bih[dir * GG + t0];
    const float bi1 = bih[dir * GG + 256 + t0];
    const float bi2 = bih[dir * GG + 512 + t0];
#pragma unroll
    for (int p = 0; p < P; p++) {
        float a0, b0, a1, b1, a2, b2;
        unpack2(acc[p][0], a0, b0);
        unpack2(acc[p][1], a1, b1);
        unpack2(acc[p][2], a2, b2);
        float* oa = gx + ((size_t)dir * M + tok0 + 2 * p) * GG;
        float* ob = oa + GG;
        oa[t0]       = a0 + bi0;  ob[t0]       = b0 + bi0;
        oa[256 + t0] = a1 + bi1;  ob[256 + t0] = b1 + bi1;
        oa[512 + t0] = a2 + bi2;  ob[512 + t0] = b2 + bi2;
    }
}

// ---------------- recurrent GRU, row-paired f32x2 ----------------
template <int IDX, int ROWS, int T>
__global__ __launch_bounds__(256, 2)
void gru_rec_kernel(const int* __restrict__ widx,
                    const float* __restrict__ gx, int gxM,
                    const float* __restrict__ wT_hh,
                    const float* __restrict__ bhh,
                    float* __restrict__ out, int nbatch) {
    constexpr int P = ROWS / 2;
    constexpr int U = 4;
    const int dir  = blockIdx.y;
    const int row0 = blockIdx.x * ROWS;
    const int t0   = threadIdx.x;

    __shared__ float2 sh2[P][HD];
#pragma unroll
    for (int p = 0; p < P; p++) sh2[p][t0] = make_float2(0.0f, 0.0f);

    const float* wbase = wT_hh + (size_t)dir * HD * GG + t0;
    const float bh0 = bhh[dir * GG + t0];
    const float bh1 = bhh[dir * GG + 256 + t0];
    const float bh2 = bhh[dir * GG + 512 + t0];
    __syncthreads();

    for (int t = 0; t < T; t++) {
        const int te = dir ? (T - 1 - t) : t;

#pragma unroll
        for (int p = 0; p < P; p++) {
            const int ra = row0 + 2 * p, rb = ra + 1;
            const long ia = IDX ? (long)widx[ra * T + te] : (long)ra * T + te;
            const long ib = IDX ? (long)widx[rb * T + te] : (long)rb * T + te;
            const float* ga = gx + ((size_t)dir * gxM + ia) * GG + t0;
            const float* gb = gx + ((size_t)dir * gxM + ib) * GG + t0;
            pf_l1(ga); pf_l1(ga + 256); pf_l1(ga + 512);
            pf_l1(gb); pf_l1(gb + 256); pf_l1(gb + 512);
        }

        u64 ah[P][3];
#pragma unroll
        for (int p = 0; p < P; p++) ah[p][0] = ah[p][1] = ah[p][2] = 0ull;

        float wA[3][U], wB[3][U];
        load_wchunk<U>(wA, wbase, 0);
#pragma unroll 1
        for (int kb = 0; kb < HD; kb += 2 * U) {
            load_wchunk<U>(wB, wbase, kb + U);
            fma_chunk<U, P, HD>(ah, wA, sh2, kb);
            if (kb + 2 * U < HD) load_wchunk<U>(wA, wbase, kb + 2 * U);
            fma_chunk<U, P, HD>(ah, wB, sh2, kb + U);
        }
        __syncthreads();

#pragma unroll
        for (int p = 0; p < P; p++) {
            const int ra = row0 + 2 * p, rb = ra + 1;
            const long ia = IDX ? (long)widx[ra * T + te] : (long)ra * T + te;
            const long ib = IDX ? (long)widx[rb * T + te] : (long)rb * T + te;
            const float* ga = gx + ((size_t)dir * gxM + ia) * GG;
            const float* gb = gx + ((size_t)dir * gxM + ib) * GG;
            const float x0a = ga[t0], x1a = ga[256 + t0], x2a = ga[512 + t0];
            const float x0b = gb[t0], x1b = gb[256 + t0], x2b = gb[512 + t0];
            float h0a, h0b, h1a, h1b, h2a, h2b;
            unpack2(ah[p][0], h0a, h0b); unpack2(ah[p][1], h1a, h1b); unpack2(ah[p][2], h2a, h2b);
            const float2 hold = sh2[p][t0];
            const float rga = sigf(x0a + h0a + bh0), rgb = sigf(x0b + h0b + bh0);
            const float za  = sigf(x1a + h1a + bh1), zb  = sigf(x1b + h1b + bh1);
            const float na  = tanhf(x2a + rga * (h2a + bh2));
            const float nb  = tanhf(x2b + rgb * (h2b + bh2));
            sh2[p][t0] = make_float2((1.0f - za) * na + za * hold.x,
                                     (1.0f - zb) * nb + zb * hold.y);
        }
        __syncthreads();
    }

#pragma unroll
    for (int p = 0; p < P; p++) {
        const float2 h = sh2[p][t0];
        out[((size_t)dir * nbatch + row0 + 2 * p) * HD + t0]     = h.x;
        out[((size_t)dir * nbatch + row0 + 2 * p + 1) * HD + t0] = h.y;
    }
}

// ---------------- review-level recurrent GRU (batch 1, scalar) ----------------
__global__ void gru_rec1_kernel(const float* __restrict__ gx,
                                const float* __restrict__ wT_hh,
                                const float* __restrict__ bhh,
                                float* __restrict__ out) {
    const int dir = blockIdx.x;
    const int t0  = threadIdx.x;
    __shared__ float sh[HD];
    sh[t0] = 0.0f;
    const float* whh = wT_hh + (size_t)dir * HD * GG;
    const float bh0 = bhh[dir * GG + t0];
    const float bh1 = bhh[dir * GG + 256 + t0];
    const float bh2 = bhh[dir * GG + 512 + t0];
    __syncthreads();

    for (int t = 0; t < NREV; t++) {
        const int te = dir ? (NREV - 1 - t) : t;
        const float* ga = gx + ((size_t)dir * NREV + te) * GG;
        const float x0 = ga[t0], x1 = ga[256 + t0], x2 = ga[512 + t0];
        float a0 = 0.0f, a1 = 0.0f, a2 = 0.0f;
#pragma unroll 8
        for (int k = 0; k < HD; k++) {
            const float hk = sh[k];
            a0 += hk * whh[(size_t)k * GG + t0];
            a1 += hk * whh[(size_t)k * GG + 256 + t0];
            a2 += hk * whh[(size_t)k * GG + 512 + t0];
        }
        const float hold = sh[t0];
        __syncthreads();
        const float r = sigf(x0 + a0 + bh0);
        const float z = sigf(x1 + a1 + bh1);
        const float n = tanhf(x2 + r * (a2 + bh2));
        sh[t0] = (1.0f - z) * n + z * hold;
        __syncthreads();
    }
    out[dir * HD + t0] = sh[t0];
}

// ---------------- p_batch / heads ----------------
__global__ void pbatch_kernel(const float* __restrict__ rev0,
                              const float* __restrict__ rev1,
                              const float* __restrict__ user_feats,
                              const float* __restrict__ uf_w,
                              float* __restrict__ pbatch) {
    int b = blockIdx.x;
    int t = threadIdx.x;
    if (t < HD) {
        pbatch[b * DREV + t] = rev0[b * HD + t] + rev1[b * HD + t];
    } else {
        int lane = t - HD;
        float v = (lane < UF) ? user_feats[b * UF + lane] : 0.0f;
        float s = v * v;
#pragma unroll
        for (int o = 16; o > 0; o >>= 1) s += __shfl_xor_sync(0xffffffffu, s, o);
        float nrm = fmaxf(sqrtf(s), 1e-12f);
        if (lane < UF) pbatch[b * DREV + HD + lane] = (v / nrm) * uf_w[lane];
    }
}

__global__ void rstars_kernel(const float* __restrict__ pbatch,
                              const float* __restrict__ w1, const float* __restrict__ b1,
                              const float* __restrict__ w2, const float* __restrict__ b2,
                              float* __restrict__ out) {
    int b = blockIdx.x;
    int j = threadIdx.x;
    float s = b1[j];
    for (int k = 0; k < DREV; k++) s += pbatch[b * DREV + k] * w1[j * DREV + k];
    float a = seluf(s) * w2[j];
    __shared__ float red[128];
    red[j] = a;
    __syncthreads();
    for (int st = 64; st > 0; st >>= 1) {
        if (j < st) red[j] += red[j + st];
        __syncthreads();
    }
    if (j == 0) out[9 + b] = red[0] + b2[0];
}

__global__ void pstars_kernel(const float* __restrict__ doc,
                              const float* __restrict__ w1, const float* __restrict__ b1,
                              const float* __restrict__ w2, const float* __restrict__ b2,
                              float* __restrict__ out) {
    int j = threadIdx.x;
    __shared__ float hid[128];
    float s = b1[j];
    for (int k = 0; k < HD; k++) s += (doc[k] + doc[HD + k]) * w1[j * HD + k];
    hid[j] = seluf(s);
    __syncthreads();
    if (j < 9) {
        float o = b2[j];
        for (int k = 0; k < 128; k++) o += hid[k] * w2[j * 128 + k];
        out[j] = o;
    }
}

// ---------------- launch ----------------
extern "C" void kernel_launch(void* const* d_in, const int* in_sizes, int n_in,
                              void* d_out, int out_size) {
    (void)in_sizes; (void)n_in; (void)out_size;
    const int*   inputs     = (const int*)d_in[0];
    const float* user_feats = (const float*)d_in[3];
    const float* embed      = (const float*)d_in[4];
    const float* wg_wih = (const float*)d_in[5];
    const float* wg_whh = (const float*)d_in[6];
    const float* wg_bih = (const float*)d_in[7];
    const float* wg_bhh = (const float*)d_in[8];
    const float* sg_wih = (const float*)d_in[9];
    const float* sg_whh = (const float*)d_in[10];
    const float* sg_bih = (const float*)d_in[11];
    const float* sg_bhh = (const float*)d_in[12];
    const float* rg_wih = (const float*)d_in[13];
    const float* rg_whh = (const float*)d_in[14];
    const float* rg_bih = (const float*)d_in[15];
    const float* rg_bhh = (const float*)d_in[16];
    const float* rfc_w1 = (const float*)d_in[17];
    const float* rfc_b1 = (const float*)d_in[18];
    const float* rfc_w2 = (const float*)d_in[19];
    const float* rfc_b2 = (const float*)d_in[20];
    const float* pfc_w1 = (const float*)d_in[21];
    const float* pfc_b1 = (const float*)d_in[22];
    const float* pfc_w2 = (const float*)d_in[23];
    const float* pfc_b2 = (const float*)d_in[24];
    const float* uf_w   = (const float*)d_in[25];
    float* out = (float*)d_out;

    float *wgThh, *sgTih, *sgThh, *rgTih, *rgThh;
    float *gxv, *gxs, *gxr, *sent, *rev, *pbatch, *doc;
    __nv_bfloat16 *wihhi, *wihlo;
    cudaGetSymbolAddress((void**)&wgThh, g_wgT_hh);
    cudaGetSymbolAddress((void**)&sgTih, g_sgT_ih);
    cudaGetSymbolAddress((void**)&sgThh, g_sgT_hh);
    cudaGetSymbolAddress((void**)&rgTih, g_rgT_ih);
    cudaGetSymbolAddress((void**)&rgThh, g_rgT_hh);
    cudaGetSymbolAddress((void**)&wihhi, g_wih_hi);
    cudaGetSymbolAddress((void**)&wihlo, g_wih_lo);
    cudaGetSymbolAddress((void**)&gxv,   g_gx_v);
    cudaGetSymbolAddress((void**)&gxs,   g_gx_s);
    cudaGetSymbolAddress((void**)&gxr,   g_gx_r);
    cudaGetSymbolAddress((void**)&sent,  g_sent);
    cudaGetSymbolAddress((void**)&rev,   g_rev);
    cudaGetSymbolAddress((void**)&pbatch,g_pbatch);
    cudaGetSymbolAddress((void**)&doc,   g_doc);

    // 0. allow large dynamic smem for the HMMA kernel
    cudaFuncSetAttribute(vocab_gemm_mma, cudaFuncAttributeMaxDynamicSharedMemorySize, SMTOT);

    // 1. weight prep
    {
        int tot, nb;
        cudaMemsetAsync(rgTih, 0, sizeof(float) * 2 * DREVP * GG);
        tot = 2 * GG * 256; nb = (tot + 255) / 256;
        transpose_kernel<<<nb, 256>>>(wg_whh, wgThh, 256, 256);
        transpose_kernel<<<nb, 256>>>(sg_wih, sgTih, 256, 256);
        transpose_kernel<<<nb, 256>>>(sg_whh, sgThh, 256, 256);
        transpose_kernel<<<nb, 256>>>(rg_whh, rgThh, 256, 256);
        tot = 2 * GG * DREV; nb = (tot + 255) / 256;
        transpose_kernel<<<nb, 256>>>(rg_wih, rgTih, DREV, DREVP);
        tot = 2 * GG * 256; nb = (tot + 255) / 256;
        wsplit_kernel<<<nb, 256>>>(wg_wih, wihhi, wihlo, tot);
    }

    // 2. word level: HMMA input gates per vocabulary row, then FFMA2 recurrent
    vocab_gemm_mma<<<dim3(NVT, 2), 256, SMTOT>>>(embed, wihhi, wihlo, wg_bih, gxv);
    gru_rec_kernel<1, 16, NWORD><<<dim3(NSENT / 16, 2), 256>>>(
        inputs, gxv, NV, wgThh, wg_bhh, sent, NSENT);

    // 3. sentence level
    gates_gemm_kernel<1, 256, 256, 16><<<dim3(NSENT / 16, 2), 256>>>(
        sent, sent + NSENT * HD, sgTih, sg_bih, gxs, NSENT);
    gru_rec_kernel<0, 2, SPR><<<dim3(NREV / 2, 2), 256>>>(
        nullptr, gxs, NSENT, sgThh, sg_bhh, rev, NREV);

    // 4-5. p_batch + r_stars head
    pbatch_kernel<<<NREV, 288>>>(rev, rev + NREV * HD, user_feats, uf_w, pbatch);
    rstars_kernel<<<NREV, 128>>>(pbatch, rfc_w1, rfc_b1, rfc_w2, rfc_b2, out);

    // 6. review level
    gates_gemm_kernel<2, DREVP, DREV, 16><<<dim3(NREV / 16, 2), 256>>>(
        pbatch, nullptr, rgTih, rg_bih, gxr, NREV);
    gru_rec1_kernel<<<2, 256>>>(gxr, rgThh, rg_bhh, doc);

    // 7. p_stars head
    pstars_kernel<<<1, 128>>>(doc, pfc_w1, pfc_b1, pfc_w2, pfc_b2, out);
}